// round 12
// baseline (speedup 1.0000x reference)
#include <cuda_runtime.h>
#include <math.h>
#include <stdint.h>

// Problem constants
#define BB    8
#define CC    512
#define NN    1024        // H*W = 32*32
#define HEADS 8
#define DK    64
#define QKVC  1536        // HEADS * DK * 3
#define SCL2E 0.18033688f // DK^-0.5 * log2(e)

// ---------------------------------------------------------------------------
// Scratch (device globals; no allocation allowed) — bf16 hi/lo planes
// ---------------------------------------------------------------------------
__device__ uint16_t g_xh[BB * CC * NN],  g_xl[BB * CC * NN];    // x split
__device__ uint16_t g_wqh[CC * QKVC],    g_wql[CC * QKVC];      // W_qkv split
__device__ uint16_t g_woh[CC * CC],      g_wol[CC * CC];        // W_out split
__device__ uint16_t g_qh[BB * NN * QKVC], g_ql[BB * NN * QKVC]; // qkv (Q pre-scaled)
__device__ uint16_t g_ah[BB * NN * CC],  g_al[BB * NN * CC];    // attention out

// ---------------------------------------------------------------------------
// Helpers
// ---------------------------------------------------------------------------
__device__ __forceinline__ float ex2(float x) {
    float y;
    asm("ex2.approx.f32 %0, %1;" : "=f"(y) : "f"(x));
    return y;
}
__device__ __forceinline__ uint32_t hi2(float f0, float f1) {
    uint32_t r;
    asm("prmt.b32 %0, %1, %2, 0x7632;" : "=r"(r)
        : "r"(__float_as_uint(f0)), "r"(__float_as_uint(f1)));
    return r;
}
__device__ __forceinline__ float hif(float f) {
    return __uint_as_float(__float_as_uint(f) & 0xFFFF0000u);
}
__device__ __forceinline__ uint32_t lo2(float f0, float f1) {
    uint32_t r;
    asm("cvt.rn.bf16x2.f32 %0, %1, %2;" : "=r"(r)
        : "f"(f1 - hif(f1)), "f"(f0 - hif(f0)));
    return r;
}

__device__ __forceinline__ void cpa16(uint32_t dst, const void* src) {
    asm volatile("cp.async.cg.shared.global [%0], [%1], 16;" :: "r"(dst), "l"(src));
}
#define CP_COMMIT() asm volatile("cp.async.commit_group;" ::: "memory")
#define CP_WAIT1()  asm volatile("cp.async.wait_group 1;" ::: "memory")
#define CP_WAIT0()  asm volatile("cp.async.wait_group 0;" ::: "memory")

__device__ __forceinline__ void ldmx4t(uint32_t addr, uint32_t& r0, uint32_t& r1,
                                       uint32_t& r2, uint32_t& r3) {
    asm volatile("ldmatrix.sync.aligned.m8n8.x4.trans.shared.b16 {%0,%1,%2,%3}, [%4];"
                 : "=r"(r0), "=r"(r1), "=r"(r2), "=r"(r3) : "r"(addr));
}
__device__ __forceinline__ void ldmx4(uint32_t addr, uint32_t* r) {
    asm volatile("ldmatrix.sync.aligned.m8n8.x4.shared.b16 {%0,%1,%2,%3}, [%4];"
                 : "=r"(r[0]), "=r"(r[1]), "=r"(r[2]), "=r"(r[3]) : "r"(addr));
}
__device__ __forceinline__ void mma16816(float* d, const uint32_t* a, const uint32_t* b) {
    asm volatile("mma.sync.aligned.m16n8k16.row.col.f32.bf16.bf16.f32 "
                 "{%0,%1,%2,%3}, {%4,%5,%6,%7}, {%8,%9}, {%0,%1,%2,%3};"
                 : "+f"(d[0]), "+f"(d[1]), "+f"(d[2]), "+f"(d[3])
                 : "r"(a[0]), "r"(a[1]), "r"(a[2]), "r"(a[3]), "r"(b[0]), "r"(b[1]));
}
__device__ __forceinline__ void mma_b(float* d, const uint32_t* a, uint32_t b0, uint32_t b1) {
    asm volatile("mma.sync.aligned.m16n8k16.row.col.f32.bf16.bf16.f32 "
                 "{%0,%1,%2,%3}, {%4,%5,%6,%7}, {%8,%9}, {%0,%1,%2,%3};"
                 : "+f"(d[0]), "+f"(d[1]), "+f"(d[2]), "+f"(d[3])
                 : "r"(a[0]), "r"(a[1]), "r"(a[2]), "r"(a[3]), "r"(b0), "r"(b1));
}

// ---------------------------------------------------------------------------
// Kernel 0: fp32 -> bf16 hi/lo plane split (pre-pass)
// ---------------------------------------------------------------------------
__global__ __launch_bounds__(256) void k_cvt(const float* __restrict__ src,
                                             int which, int n4)
{
    uint16_t *h, *l;
    if (which == 0)      { h = g_xh;  l = g_xl;  }
    else if (which == 1) { h = g_wqh; l = g_wql; }
    else                 { h = g_woh; l = g_wol; }
    int i = blockIdx.x * blockDim.x + threadIdx.x;
    if (i < n4) {
        float4 v = ((const float4*)src)[i];
        ((uint2*)h)[i] = make_uint2(hi2(v.x, v.y), hi2(v.z, v.w));
        ((uint2*)l)[i] = make_uint2(lo2(v.x, v.y), lo2(v.z, v.w));
    }
}

// ---------------------------------------------------------------------------
// Kernel 1: QKV GEMM, tensor cores (bf16x3), cp.async 3-stage, 4 warps,
// warp tile 64x64.  Output bf16 hi/lo planes, Q pre-scaled.
// ---------------------------------------------------------------------------
#define KBYTES  8704            // one plane: 32 * 272 B
#define QK_STG  (4 * KBYTES)    // 34816 B per stage
#define QK_SMEM (3 * QK_STG)    // 104448 B

__global__ __launch_bounds__(128) void k_qkv(const float* __restrict__ bq)
{
    extern __shared__ __align__(16) uint16_t smq[];
    const int tid  = threadIdx.x;
    const int lane = tid & 31;
    const int wid  = tid >> 5;          // 0..3
    const int bx   = blockIdx.x;        // c tile 0..11
    const int by   = blockIdx.y;        // m tile 0..63
    const int b    = by >> 3;
    const int n0   = (by & 7) << 7;
    const int c0   = bx * 128;
    const uint32_t sbase = (uint32_t)__cvta_generic_to_shared(smq);

    // loader: row lk (0..31), 32 u16 per plane per thread
    const int lk  = tid >> 2;
    const int lmf = (tid & 3) * 32;
    const size_t aG = (size_t)b * CC * NN + n0 + lmf + (size_t)lk * NN;
    const size_t wG = (size_t)c0 + lmf + (size_t)lk * QKVC;
    const uint32_t dA = (uint32_t)(lk * 136 + lmf) * 2;

    const int wm = wid >> 1;            // 0..1
    const int wn = wid & 1;             // 0..1
    const uint32_t aOff = ((lane & 7) + ((lane >> 4) << 3)) * 272
                        + (uint32_t)(wm * 128) + ((lane >> 3) & 1) * 16;
    const uint32_t bOff = ((lane & 7) + (((lane >> 3) & 1) << 3)) * 272
                        + (uint32_t)(wn * 128) + (lane >> 4) * 16;

    float acc[4][8][4];
#pragma unroll
    for (int i = 0; i < 4; i++)
#pragma unroll
        for (int j = 0; j < 8; j++)
#pragma unroll
            for (int e = 0; e < 4; e++) acc[i][j][e] = 0.f;

#define QK_ISSUE(s) do {                                                      \
        uint32_t st = sbase + ((s) % 3) * QK_STG;                             \
        size_t ko = (size_t)(s) * 32;                                         \
        const uint16_t* ah = &g_xh[aG + ko * NN];                             \
        const uint16_t* al = &g_xl[aG + ko * NN];                             \
        const uint16_t* wh = &g_wqh[wG + ko * QKVC];                          \
        const uint16_t* wl = &g_wql[wG + ko * QKVC];                          \
        _Pragma("unroll")                                                     \
        for (int cc = 0; cc < 4; cc++) {                                      \
            cpa16(st + dA + cc * 16,              ah + cc * 8);               \
            cpa16(st + dA + KBYTES + cc * 16,     al + cc * 8);               \
            cpa16(st + dA + 2 * KBYTES + cc * 16, wh + cc * 8);               \
            cpa16(st + dA + 3 * KBYTES + cc * 16, wl + cc * 8);               \
        }                                                                     \
    } while (0)

    QK_ISSUE(0); CP_COMMIT();
    QK_ISSUE(1); CP_COMMIT();

    for (int s = 0; s < 16; s++) {
        if (s < 15) CP_WAIT1(); else CP_WAIT0();
        __syncthreads();
        if (s + 2 < 16) { QK_ISSUE(s + 2); CP_COMMIT(); }

        const uint32_t base = sbase + (uint32_t)(s % 3) * QK_STG;
#pragma unroll
        for (int ks = 0; ks < 2; ks++) {
            uint32_t ahi[4][4], alo[4][4], bhi[8][2], blo[8][2];
#pragma unroll
            for (int i = 0; i < 4; i++) {
                uint32_t addr = base + aOff + ks * 4352 + i * 32;
                ldmx4t(addr, ahi[i][0], ahi[i][1], ahi[i][2], ahi[i][3]);
                ldmx4t(addr + KBYTES, alo[i][0], alo[i][1], alo[i][2], alo[i][3]);
            }
#pragma unroll
            for (int j2 = 0; j2 < 4; j2++) {
                uint32_t addr = base + 2 * KBYTES + bOff + ks * 4352 + j2 * 32;
                ldmx4t(addr, bhi[2 * j2][0], bhi[2 * j2][1], bhi[2 * j2 + 1][0], bhi[2 * j2 + 1][1]);
                ldmx4t(addr + KBYTES, blo[2 * j2][0], blo[2 * j2][1], blo[2 * j2 + 1][0], blo[2 * j2 + 1][1]);
            }
#pragma unroll
            for (int i = 0; i < 4; i++)
#pragma unroll
                for (int jn = 0; jn < 8; jn++) {
                    mma16816(acc[i][jn], ahi[i], bhi[jn]);
                    mma16816(acc[i][jn], ahi[i], blo[jn]);
                    mma16816(acc[i][jn], alo[i], bhi[jn]);
                }
        }
    }

    // ---- epilogue: bias, pre-scale Q columns, split hi/lo ----
    const int g   = lane >> 2;
    const int tig = lane & 3;
#pragma unroll
    for (int i = 0; i < 4; i++) {
        int m = by * 128 + wm * 64 + i * 16 + g;
#pragma unroll
        for (int jn = 0; jn < 8; jn++) {
            int c = c0 + wn * 64 + jn * 8 + tig * 2;
            float2 bias = *(const float2*)&bq[c];
            float sc = ((c % 192) < 64) ? SCL2E : 1.f;
            float v0 = (acc[i][jn][0] + bias.x) * sc;
            float v1 = (acc[i][jn][1] + bias.y) * sc;
            float v2 = (acc[i][jn][2] + bias.x) * sc;
            float v3 = (acc[i][jn][3] + bias.y) * sc;
            size_t i0 = (size_t)m * QKVC + c;
            size_t i1 = (size_t)(m + 8) * QKVC + c;
            *(uint32_t*)&g_qh[i0] = hi2(v0, v1);
            *(uint32_t*)&g_ql[i0] = lo2(v0, v1);
            *(uint32_t*)&g_qh[i1] = hi2(v2, v3);
            *(uint32_t*)&g_ql[i1] = lo2(v2, v3);
        }
    }
}

// ---------------------------------------------------------------------------
// Kernel 2: attention, tensor cores (bf16x3), 4 warps x 32 q-rows,
// K/V tiles of 64 keys double-buffered (smem 110.6KB -> 2 CTA/SM).
// ---------------------------------------------------------------------------
#define A_QLO   9216            // u16 offsets
#define A_ST0   18432           // stage region start
#define A_STG   18432           // u16 per stage (4 planes * 64*72)
#define A_KLOo  4608            // within stage
#define A_VHIo  9216
#define A_VLOo  13824
#define A_SMEM_BYTES ((A_ST0 + 2 * A_STG) * 2)   // 110592 B

__global__ __launch_bounds__(128) void k_attn()
{
    extern __shared__ __align__(16) uint16_t sma[];
    const int tid  = threadIdx.x;
    const int lane = tid & 31;
    const int wid  = tid >> 5;     // 0..3
    const int qt   = blockIdx.x;   // 0..7
    const int h    = blockIdx.y;
    const int b    = blockIdx.z;
    const size_t head = (size_t)b * NN * QKVC + (size_t)h * (3 * DK);
    const uint32_t sb = (uint32_t)__cvta_generic_to_shared(sma);

    // Q loader: one row per thread (0..127), 64 u16/plane = 8 chunks
    const uint32_t dQ = (uint32_t)(tid * 72) * 2;
#define AT_ISSUE_Q() do {                                                     \
        size_t r = head + (size_t)(qt * 128 + tid) * QKVC;                    \
        const uint16_t* qh_ = &g_qh[r];                                       \
        const uint16_t* ql_ = &g_ql[r];                                       \
        _Pragma("unroll")                                                     \
        for (int cc = 0; cc < 8; cc++) {                                      \
            cpa16(sb + dQ + cc * 16, qh_ + cc * 8);                           \
            cpa16(sb + dQ + A_QLO * 2 + cc * 16, ql_ + cc * 8);               \
        }                                                                     \
    } while (0)

    // KV loader: key row = tid>>1 (0..63), half-row 32 u16
    const int lrow = tid >> 1;
    const int loff = (tid & 1) * 32;
    const uint32_t dKV = (uint32_t)(lrow * 72 + loff) * 2;
#define AT_ISSUE_KV(kt) do {                                                  \
        uint32_t st = sb + (A_ST0 + ((kt) & 1) * A_STG) * 2;                  \
        size_t r = head + (size_t)((kt) * 64 + lrow) * QKVC + loff;           \
        const uint16_t* kh_ = &g_qh[r + 64];                                  \
        const uint16_t* kl_ = &g_ql[r + 64];                                  \
        const uint16_t* vh_ = &g_qh[r + 128];                                 \
        const uint16_t* vl_ = &g_ql[r + 128];                                 \
        _Pragma("unroll")                                                     \
        for (int cc = 0; cc < 4; cc++) {                                      \
            cpa16(st + dKV + cc * 16,                kh_ + cc * 8);           \
            cpa16(st + dKV + A_KLOo * 2 + cc * 16,   kl_ + cc * 8);           \
            cpa16(st + dKV + A_VHIo * 2 + cc * 16,   vh_ + cc * 8);           \
            cpa16(st + dKV + A_VLOo * 2 + cc * 16,   vl_ + cc * 8);           \
        }                                                                     \
    } while (0)

    AT_ISSUE_Q(); AT_ISSUE_KV(0); CP_COMMIT();
    AT_ISSUE_KV(1); CP_COMMIT();

    const uint32_t kOff = ((lane & 7) + ((lane >> 4) << 3)) * 144
                        + ((lane >> 3) & 1) * 16;                 // non-trans (K)
    const uint32_t vOff = ((lane & 7) + (((lane >> 3) & 1) << 3)) * 144
                        + (lane >> 4) * 16;                        // trans (V)

    uint32_t qf[2][2][4][4];   // [rowtile][plane][kstep][frag]
    float oacc[2][8][4];
#pragma unroll
    for (int rt = 0; rt < 2; rt++)
#pragma unroll
        for (int i = 0; i < 8; i++)
#pragma unroll
            for (int e = 0; e < 4; e++) oacc[rt][i][e] = 0.f;
    float li[2][2] = {{0.f, 0.f}, {0.f, 0.f}};

    for (int kt = 0; kt < 16; kt++) {
        if (kt < 15) CP_WAIT1(); else CP_WAIT0();
        __syncthreads();

        if (kt == 0) {
#pragma unroll
            for (int rt = 0; rt < 2; rt++) {
                const uint32_t qa = sb + (wid * 32 + rt * 16 + (lane & 15)) * 144
                                  + (lane >> 4) * 16;
#pragma unroll
                for (int j = 0; j < 4; j++) {
                    ldmx4(qa + j * 32, qf[rt][0][j]);
                    ldmx4(qa + j * 32 + A_QLO * 2, qf[rt][1][j]);
                }
            }
        }

        const uint32_t stb = sb + (A_ST0 + (kt & 1) * A_STG) * 2;
        const uint32_t kB = stb + kOff;
        const uint32_t vB = stb + A_VHIo * 2 + vOff;

#pragma unroll
        for (int nt2 = 0; nt2 < 4; nt2++) {
            float s[2][2][4];   // [rowtile][n8][4]
#pragma unroll
            for (int rt = 0; rt < 2; rt++)
#pragma unroll
                for (int t = 0; t < 2; t++)
#pragma unroll
                    for (int e = 0; e < 4; e++) s[rt][t][e] = 0.f;

#pragma unroll
            for (int j = 0; j < 4; j++) {
                uint32_t kh[4], kl[4];
                uint32_t a = kB + nt2 * (16 * 144) + j * 32;
                ldmx4(a, kh);
                ldmx4(a + A_KLOo * 2, kl);
#pragma unroll
                for (int rt = 0; rt < 2; rt++) {
                    mma_b(s[rt][0], qf[rt][0][j], kh[0], kh[1]);
                    mma_b(s[rt][0], qf[rt][0][j], kl[0], kl[1]);
                    mma_b(s[rt][0], qf[rt][1][j], kh[0], kh[1]);
                    mma_b(s[rt][1], qf[rt][0][j], kh[2], kh[3]);
                    mma_b(s[rt][1], qf[rt][0][j], kl[2], kl[3]);
                    mma_b(s[rt][1], qf[rt][1][j], kh[2], kh[3]);
                }
            }

            uint32_t ph[2][4], pl[2][4];
#pragma unroll
            for (int rt = 0; rt < 2; rt++) {
#pragma unroll
                for (int t = 0; t < 2; t++)
#pragma unroll
                    for (int e = 0; e < 4; e++) s[rt][t][e] = ex2(s[rt][t][e]);
                li[rt][0] += (s[rt][0][0] + s[rt][0][1]) + (s[rt][1][0] + s[rt][1][1]);
                li[rt][1] += (s[rt][0][2] + s[rt][0][3]) + (s[rt][1][2] + s[rt][1][3]);
                ph[rt][0] = hi2(s[rt][0][0], s[rt][0][1]); ph[rt][1] = hi2(s[rt][0][2], s[rt][0][3]);
                ph[rt][2] = hi2(s[rt][1][0], s[rt][1][1]); ph[rt][3] = hi2(s[rt][1][2], s[rt][1][3]);
                pl[rt][0] = lo2(s[rt][0][0], s[rt][0][1]); pl[rt][1] = lo2(s[rt][0][2], s[rt][0][3]);
                pl[rt][2] = lo2(s[rt][1][0], s[rt][1][1]); pl[rt][3] = lo2(s[rt][1][2], s[rt][1][3]);
            }

#pragma unroll
            for (int dt2 = 0; dt2 < 4; dt2++) {
                uint32_t vh0, vh1, vh2, vh3, vl0, vl1, vl2, vl3;
                uint32_t a = vB + nt2 * (16 * 144) + dt2 * 32;
                ldmx4t(a, vh0, vh1, vh2, vh3);
                ldmx4t(a + (A_VLOo - A_VHIo) * 2, vl0, vl1, vl2, vl3);
#pragma unroll
                for (int rt = 0; rt < 2; rt++) {
                    mma_b(oacc[rt][2 * dt2],     ph[rt], vh0, vh1);
                    mma_b(oacc[rt][2 * dt2],     ph[rt], vl0, vl1);
                    mma_b(oacc[rt][2 * dt2],     pl[rt], vh0, vh1);
                    mma_b(oacc[rt][2 * dt2 + 1], ph[rt], vh2, vh3);
                    mma_b(oacc[rt][2 * dt2 + 1], ph[rt], vl2, vl3);
                    mma_b(oacc[rt][2 * dt2 + 1], pl[rt], vh2, vh3);
                }
            }
        }

        __syncthreads();
        if (kt + 2 < 16) { AT_ISSUE_KV(kt + 2); CP_COMMIT(); }
    }

    // ---- reduce row sums, normalize, write planes ----
#pragma unroll
    for (int rt = 0; rt < 2; rt++)
#pragma unroll
        for (int hh = 0; hh < 2; hh++) {
            li[rt][hh] += __shfl_xor_sync(0xffffffffu, li[rt][hh], 1);
            li[rt][hh] += __shfl_xor_sync(0xffffffffu, li[rt][hh], 2);
        }

    const int g   = lane >> 2;
    const int tig = lane & 3;
#pragma unroll
    for (int rt = 0; rt < 2; rt++) {
        const float inv0 = 1.f / li[rt][0];
        const float inv1 = 1.f / li[rt][1];
        const int row = qt * 128 + wid * 32 + rt * 16 + g;
        const size_t r0 = (size_t)(b * NN + row) * CC + h * 64 + tig * 2;
        const size_t r1 = r0 + (size_t)8 * CC;
#pragma unroll
        for (int dt = 0; dt < 8; dt++) {
            float a0 = oacc[rt][dt][0] * inv0, a1 = oacc[rt][dt][1] * inv0;
            float a2 = oacc[rt][dt][2] * inv1, a3 = oacc[rt][dt][3] * inv1;
            *(uint32_t*)&g_ah[r0 + dt * 8] = hi2(a0, a1);
            *(uint32_t*)&g_al[r0 + dt * 8] = lo2(a0, a1);
            *(uint32_t*)&g_ah[r1 + dt * 8] = hi2(a2, a3);
            *(uint32_t*)&g_al[r1 + dt * 8] = lo2(a2, a3);
        }
    }
}

// ---------------------------------------------------------------------------
// Kernel 3: out = att @ W_out + b_out + residual, 4 warps, warp tile 64x64,
// cp.async 3-stage; smem-transpose epilogue with fused bias+residual.
// FIX vs R11: A loader now fills the FULL 32-u16 stage row per thread.
// ---------------------------------------------------------------------------
#define PJ_ALO    10240    // byte offsets within a stage
#define PJ_BHI    20480
#define PJ_BLO    29184
#define PJ_STAGEB 37888
#define PJ_SMEM   (3 * PJ_STAGEB)   // 113664 B

__global__ __launch_bounds__(128) void k_proj(const float* __restrict__ bo,
                                              const float* __restrict__ x,
                                              float* __restrict__ out)
{
    extern __shared__ __align__(16) uint16_t smp[];
    const int tid  = threadIdx.x;
    const int lane = tid & 31;
    const int wid  = tid >> 5;      // 0..3
    const int bx   = blockIdx.x;    // bn tile 0..63
    const int by   = blockIdx.y;    // c tile 0..3
    const int b    = bx >> 3;
    const int c0   = by * 128;
    const int bn0  = bx * 128;
    const uint32_t sb = (uint32_t)__cvta_generic_to_shared(smp);

    // loaders
    const size_t aG = (size_t)(bn0 + tid) * CC;           // row tid, k from s*32
    const uint32_t dAp = (uint32_t)(tid * 40) * 2;
    const int bk = tid >> 2;
    const int bn = (tid & 3) * 32;
    const size_t bG = (size_t)bk * CC + c0 + bn;
    const uint32_t dBp = PJ_BHI + (uint32_t)(bk * 136 + bn) * 2;

#define PJ_ISSUE(s) do {                                                      \
        uint32_t st = sb + ((s) % 3) * PJ_STAGEB;                             \
        const uint16_t* ah = &g_ah[aG + (s) * 32];                            \
        const uint16_t* al = &g_al[aG + (s) * 32];                            \
        const uint16_t* bh = &g_woh[bG + (size_t)(s) * 32 * CC];              \
        const uint16_t* bl = &g_wol[bG + (size_t)(s) * 32 * CC];              \
        _Pragma("unroll")                                                     \
        for (int cc = 0; cc < 4; cc++) {                                      \
            cpa16(st + dAp + cc * 16,          ah + cc * 8);                  \
            cpa16(st + dAp + PJ_ALO + cc * 16, al + cc * 8);                  \
            cpa16(st + dBp + cc * 16,          bh + cc * 8);                  \
            cpa16(st + dBp + 8704 + cc * 16,   bl + cc * 8);                  \
        }                                                                     \
    } while (0)

    const int wm = wid >> 1;
    const int wn = wid & 1;
    const uint32_t aOff = (wm * 64 + (lane & 15)) * 80 + (lane >> 4) * 16;
    const uint32_t bOff = PJ_BHI + ((lane & 7) + (((lane >> 3) & 1) << 3)) * 272
                        + (uint32_t)(wn * 128) + (lane >> 4) * 16;

    float acc[4][8][4];
#pragma unroll
    for (int i = 0; i < 4; i++)
#pragma unroll
        for (int j = 0; j < 8; j++)
#pragma unroll
            for (int e = 0; e < 4; e++) acc[i][j][e] = 0.f;

    PJ_ISSUE(0); CP_COMMIT();
    PJ_ISSUE(1); CP_COMMIT();

    for (int s = 0; s < 16; s++) {
        if (s < 15) CP_WAIT1(); else CP_WAIT0();
        __syncthreads();
        if (s + 2 < 16) { PJ_ISSUE(s + 2); CP_COMMIT(); }

        const uint32_t base = sb + (uint32_t)(s % 3) * PJ_STAGEB;
#pragma unroll
        for (int ks = 0; ks < 2; ks++) {
            uint32_t ahi[4][4], alo[4][4], bhi[8][2], blo[8][2];
#pragma unroll
            for (int i = 0; i < 4; i++) {
                uint32_t a = base + aOff + i * (16 * 80) + ks * 32;
                ldmx4(a, ahi[i]);
                ldmx4(a + PJ_ALO, alo[i]);
            }
#pragma unroll
            for (int j2 = 0; j2 < 4; j2++) {
                uint32_t a = base + bOff + ks * 4352 + j2 * 32;
                ldmx4t(a, bhi[2 * j2][0], bhi[2 * j2][1], bhi[2 * j2 + 1][0], bhi[2 * j2 + 1][1]);
                ldmx4t(a + 8704, blo[2 * j2][0], blo[2 * j2][1], blo[2 * j2 + 1][0], blo[2 * j2 + 1][1]);
            }
#pragma unroll
            for (int i = 0; i < 4; i++)
#pragma unroll
                for (int jn = 0; jn < 8; jn++) {
                    mma16816(acc[i][jn], ahi[i], bhi[jn]);
                    mma16816(acc[i][jn], ahi[i], blo[jn]);
                    mma16816(acc[i][jn], alo[i], bhi[jn]);
                }
        }
    }

    // ---- epilogue: transpose via smem, fused bias + residual ----
    __syncthreads();
    float* S = (float*)smp;   // [128 c][stride 132] of m
    const int g   = lane >> 2;
    const int tig = lane & 3;
#pragma unroll
    for (int i = 0; i < 4; i++) {
        int m_l = wm * 64 + i * 16 + g;
#pragma unroll
        for (int jn = 0; jn < 8; jn++) {
            int c_l = wn * 64 + jn * 8 + tig * 2;
            S[c_l * 132 + m_l]           = acc[i][jn][0];
            S[(c_l + 1) * 132 + m_l]     = acc[i][jn][1];
            S[c_l * 132 + m_l + 8]       = acc[i][jn][2];
            S[(c_l + 1) * 132 + m_l + 8] = acc[i][jn][3];
        }
    }
    __syncthreads();
    {
        const int c_l  = tid;            // 0..127
        const int c    = c0 + c_l;
        const float bias = bo[c];
        const int n0 = (bx & 7) * 128;
        const size_t basep = (size_t)b * CC * NN + (size_t)c * NN + n0;
#pragma unroll
        for (int i = 0; i < 32; i++) {
            float4 v  = *(float4*)&S[c_l * 132 + 4 * i];
            float4 xr = *(const float4*)&x[basep + 4 * i];
            v.x += bias + xr.x; v.y += bias + xr.y;
            v.z += bias + xr.z; v.w += bias + xr.w;
            *(float4*)&out[basep + 4 * i] = v;
        }
    }
}

// ---------------------------------------------------------------------------
extern "C" void kernel_launch(void* const* d_in, const int* in_sizes, int n_in,
                              void* d_out, int out_size)
{
    const float* x  = (const float*)d_in[0];
    const float* Wq = (const float*)d_in[1];
    const float* bq = (const float*)d_in[2];
    const float* Wo = (const float*)d_in[3];
    const float* bo = (const float*)d_in[4];
    float* out = (float*)d_out;

    k_cvt<<<(BB * CC * NN / 4 + 255) / 256, 256>>>(x, 0, BB * CC * NN / 4);
    k_cvt<<<(CC * QKVC / 4 + 255) / 256, 256>>>(Wq, 1, CC * QKVC / 4);
    k_cvt<<<(CC * CC / 4 + 255) / 256, 256>>>(Wo, 2, CC * CC / 4);

    cudaFuncSetAttribute(k_qkv, cudaFuncAttributeMaxDynamicSharedMemorySize, QK_SMEM);
    k_qkv<<<dim3(12, 64), 128, QK_SMEM>>>(bq);

    cudaFuncSetAttribute(k_attn, cudaFuncAttributeMaxDynamicSharedMemorySize, A_SMEM_BYTES);
    k_attn<<<dim3(8, HEADS, BB), 128, A_SMEM_BYTES>>>();

    cudaFuncSetAttribute(k_proj, cudaFuncAttributeMaxDynamicSharedMemorySize, PJ_SMEM);
    k_proj<<<dim3(64, 4), 128, PJ_SMEM>>>(bo, x, out);
}

// round 13
// speedup vs baseline: 1.1536x; 1.1536x over previous
#include <cuda_runtime.h>
#include <math.h>
#include <stdint.h>

// Problem constants
#define BB    8
#define CC    512
#define NN    1024        // H*W = 32*32
#define HEADS 8
#define DK    64
#define QKVC  1536        // HEADS * DK * 3
#define SCL2E 0.18033688f // DK^-0.5 * log2(e)

// ---------------------------------------------------------------------------
// Scratch (device globals; no allocation allowed) — bf16 hi/lo planes
// ---------------------------------------------------------------------------
__device__ uint16_t g_xh[BB * CC * NN],  g_xl[BB * CC * NN];    // x split
__device__ uint16_t g_wqh[CC * QKVC],    g_wql[CC * QKVC];      // W_qkv split
__device__ uint16_t g_woh[CC * CC],      g_wol[CC * CC];        // W_out split
__device__ uint16_t g_qh[BB * NN * QKVC], g_ql[BB * NN * QKVC]; // qkv (Q pre-scaled)
__device__ uint16_t g_ah[BB * NN * CC],  g_al[BB * NN * CC];    // attention out

// ---------------------------------------------------------------------------
// Helpers
// ---------------------------------------------------------------------------
__device__ __forceinline__ float ex2(float x) {
    float y;
    asm("ex2.approx.f32 %0, %1;" : "=f"(y) : "f"(x));
    return y;
}
__device__ __forceinline__ uint32_t hi2(float f0, float f1) {
    uint32_t r;
    asm("prmt.b32 %0, %1, %2, 0x7632;" : "=r"(r)
        : "r"(__float_as_uint(f0)), "r"(__float_as_uint(f1)));
    return r;
}
__device__ __forceinline__ float hif(float f) {
    return __uint_as_float(__float_as_uint(f) & 0xFFFF0000u);
}
__device__ __forceinline__ uint32_t lo2(float f0, float f1) {
    uint32_t r;
    asm("cvt.rn.bf16x2.f32 %0, %1, %2;" : "=r"(r)
        : "f"(f1 - hif(f1)), "f"(f0 - hif(f0)));
    return r;
}

__device__ __forceinline__ void cpa16(uint32_t dst, const void* src) {
    asm volatile("cp.async.cg.shared.global [%0], [%1], 16;" :: "r"(dst), "l"(src));
}
#define CP_COMMIT() asm volatile("cp.async.commit_group;" ::: "memory")
#define CP_WAIT1()  asm volatile("cp.async.wait_group 1;" ::: "memory")
#define CP_WAIT0()  asm volatile("cp.async.wait_group 0;" ::: "memory")

__device__ __forceinline__ void ldmx4t(uint32_t addr, uint32_t& r0, uint32_t& r1,
                                       uint32_t& r2, uint32_t& r3) {
    asm volatile("ldmatrix.sync.aligned.m8n8.x4.trans.shared.b16 {%0,%1,%2,%3}, [%4];"
                 : "=r"(r0), "=r"(r1), "=r"(r2), "=r"(r3) : "r"(addr));
}
__device__ __forceinline__ void ldmx4(uint32_t addr, uint32_t* r) {
    asm volatile("ldmatrix.sync.aligned.m8n8.x4.shared.b16 {%0,%1,%2,%3}, [%4];"
                 : "=r"(r[0]), "=r"(r[1]), "=r"(r[2]), "=r"(r[3]) : "r"(addr));
}
__device__ __forceinline__ void mma16816(float* d, const uint32_t* a, const uint32_t* b) {
    asm volatile("mma.sync.aligned.m16n8k16.row.col.f32.bf16.bf16.f32 "
                 "{%0,%1,%2,%3}, {%4,%5,%6,%7}, {%8,%9}, {%0,%1,%2,%3};"
                 : "+f"(d[0]), "+f"(d[1]), "+f"(d[2]), "+f"(d[3])
                 : "r"(a[0]), "r"(a[1]), "r"(a[2]), "r"(a[3]), "r"(b[0]), "r"(b[1]));
}
__device__ __forceinline__ void mma_b(float* d, const uint32_t* a, uint32_t b0, uint32_t b1) {
    asm volatile("mma.sync.aligned.m16n8k16.row.col.f32.bf16.bf16.f32 "
                 "{%0,%1,%2,%3}, {%4,%5,%6,%7}, {%8,%9}, {%0,%1,%2,%3};"
                 : "+f"(d[0]), "+f"(d[1]), "+f"(d[2]), "+f"(d[3])
                 : "r"(a[0]), "r"(a[1]), "r"(a[2]), "r"(a[3]), "r"(b0), "r"(b1));
}

// ---------------------------------------------------------------------------
// Kernel 0: fp32 -> bf16 hi/lo plane split (pre-pass)
// ---------------------------------------------------------------------------
__global__ __launch_bounds__(256) void k_cvt(const float* __restrict__ src,
                                             int which, int n4)
{
    uint16_t *h, *l;
    if (which == 0)      { h = g_xh;  l = g_xl;  }
    else if (which == 1) { h = g_wqh; l = g_wql; }
    else                 { h = g_woh; l = g_wol; }
    int i = blockIdx.x * blockDim.x + threadIdx.x;
    if (i < n4) {
        float4 v = ((const float4*)src)[i];
        ((uint2*)h)[i] = make_uint2(hi2(v.x, v.y), hi2(v.z, v.w));
        ((uint2*)l)[i] = make_uint2(lo2(v.x, v.y), lo2(v.z, v.w));
    }
}

// ---------------------------------------------------------------------------
// Kernel 1: QKV GEMM, tensor cores (bf16x3), cp.async 3-stage, 8 warps,
// warp tile 64x32 (R10 version, 128us).  Output bf16 hi/lo planes, Q scaled.
// ---------------------------------------------------------------------------
#define KBYTES  8704            // one plane: 32 * 272 B
#define QK_STG  (4 * KBYTES)    // 34816 B per stage
#define QK_SMEM (3 * QK_STG)    // 104448 B

__global__ __launch_bounds__(256) void k_qkv(const float* __restrict__ bq)
{
    extern __shared__ __align__(16) uint16_t smq[];
    const int tid  = threadIdx.x;
    const int lane = tid & 31;
    const int wid  = tid >> 5;
    const int bx   = blockIdx.x;          // c tile 0..11
    const int by   = blockIdx.y;          // m tile 0..63
    const int b    = by >> 3;
    const int n0   = (by & 7) << 7;
    const int c0   = bx * 128;
    const uint32_t sbase = (uint32_t)__cvta_generic_to_shared(smq);

    // loader mapping: row lk (0..31), 16 u16 (32B) per plane per matrix
    const int lk  = tid >> 3;
    const int lmf = (tid & 7) * 16;
    const size_t aG = (size_t)b * CC * NN + n0 + lmf + (size_t)lk * NN;
    const size_t wG = (size_t)c0 + lmf + (size_t)lk * QKVC;
    const uint32_t dA = (uint32_t)(lk * 136 + lmf) * 2;

    const int wm = wid >> 2;
    const int wn = wid & 3;
    const uint32_t aOff = ((lane & 7) + ((lane >> 4) << 3)) * 272
                        + (uint32_t)(wm * 128) + ((lane >> 3) & 1) * 16;
    const uint32_t bOff = ((lane & 7) + (((lane >> 3) & 1) << 3)) * 272
                        + (uint32_t)(wn * 64) + (lane >> 4) * 16;

    float acc[4][4][4];
#pragma unroll
    for (int i = 0; i < 4; i++)
#pragma unroll
        for (int j = 0; j < 4; j++)
#pragma unroll
            for (int e = 0; e < 4; e++) acc[i][j][e] = 0.f;

#define QK_ISSUE(s) do {                                                      \
        uint32_t st = sbase + ((s) % 3) * QK_STG;                             \
        size_t ko = (size_t)(s) * 32;                                         \
        const uint16_t* ah = &g_xh[aG + ko * NN];                             \
        const uint16_t* al = &g_xl[aG + ko * NN];                             \
        const uint16_t* wh = &g_wqh[wG + ko * QKVC];                          \
        const uint16_t* wl = &g_wql[wG + ko * QKVC];                          \
        cpa16(st + dA, ah);                   cpa16(st + dA + 16, ah + 8);    \
        cpa16(st + dA + KBYTES, al);          cpa16(st + dA + KBYTES + 16, al + 8); \
        cpa16(st + dA + 2 * KBYTES, wh);      cpa16(st + dA + 2 * KBYTES + 16, wh + 8); \
        cpa16(st + dA + 3 * KBYTES, wl);      cpa16(st + dA + 3 * KBYTES + 16, wl + 8); \
    } while (0)

    QK_ISSUE(0); CP_COMMIT();
    QK_ISSUE(1); CP_COMMIT();

    for (int s = 0; s < 16; s++) {
        if (s < 15) CP_WAIT1(); else CP_WAIT0();
        __syncthreads();
        if (s + 2 < 16) { QK_ISSUE(s + 2); CP_COMMIT(); }

        const uint32_t base = sbase + (uint32_t)(s % 3) * QK_STG;
#pragma unroll
        for (int ks = 0; ks < 2; ks++) {
            uint32_t ahi[4][4], alo[4][4], bhi[4][2], blo[4][2];
#pragma unroll
            for (int i = 0; i < 4; i++) {
                uint32_t addr = base + aOff + ks * 4352 + i * 32;
                ldmx4t(addr, ahi[i][0], ahi[i][1], ahi[i][2], ahi[i][3]);
                ldmx4t(addr + KBYTES, alo[i][0], alo[i][1], alo[i][2], alo[i][3]);
            }
#pragma unroll
            for (int j2 = 0; j2 < 2; j2++) {
                uint32_t addr = base + 2 * KBYTES + bOff + ks * 4352 + j2 * 32;
                ldmx4t(addr, bhi[2 * j2][0], bhi[2 * j2][1], bhi[2 * j2 + 1][0], bhi[2 * j2 + 1][1]);
                ldmx4t(addr + KBYTES, blo[2 * j2][0], blo[2 * j2][1], blo[2 * j2 + 1][0], blo[2 * j2 + 1][1]);
            }
#pragma unroll
            for (int i = 0; i < 4; i++)
#pragma unroll
                for (int jn = 0; jn < 4; jn++) {
                    mma16816(acc[i][jn], ahi[i], bhi[jn]);
                    mma16816(acc[i][jn], ahi[i], blo[jn]);
                    mma16816(acc[i][jn], alo[i], bhi[jn]);
                }
        }
    }

    // ---- epilogue: bias, pre-scale Q columns, split hi/lo ----
    const int g   = lane >> 2;
    const int tig = lane & 3;
#pragma unroll
    for (int i = 0; i < 4; i++) {
        int m = by * 128 + wm * 64 + i * 16 + g;
#pragma unroll
        for (int jn = 0; jn < 4; jn++) {
            int c = c0 + wn * 32 + jn * 8 + tig * 2;
            float2 bias = *(const float2*)&bq[c];
            float sc = ((c % 192) < 64) ? SCL2E : 1.f;
            float v0 = (acc[i][jn][0] + bias.x) * sc;
            float v1 = (acc[i][jn][1] + bias.y) * sc;
            float v2 = (acc[i][jn][2] + bias.x) * sc;
            float v3 = (acc[i][jn][3] + bias.y) * sc;
            size_t i0 = (size_t)m * QKVC + c;
            size_t i1 = (size_t)(m + 8) * QKVC + c;
            *(uint32_t*)&g_qh[i0] = hi2(v0, v1);
            *(uint32_t*)&g_ql[i0] = lo2(v0, v1);
            *(uint32_t*)&g_qh[i1] = hi2(v2, v3);
            *(uint32_t*)&g_ql[i1] = lo2(v2, v3);
        }
    }
}

// ---------------------------------------------------------------------------
// Kernel 2: attention, tensor cores (bf16x3), 8 warps x 16 q-rows,
// K/V stages of 64 keys double-buffered: smem 110.6KB -> 2 CTAs/SM (16 warps).
// ---------------------------------------------------------------------------
#define A_QLO   9216            // u16 offsets
#define A_ST0   18432           // stage region start (u16)
#define A_STG   18432           // u16 per stage (4 planes * 64*72)
#define A_KLOo  4608            // within stage (u16)
#define A_VHIo  9216
#define A_VLOo  13824
#define A_SMEM_BYTES ((A_ST0 + 2 * A_STG) * 2)   // 110592 B

__global__ __launch_bounds__(256, 2) void k_attn()
{
    extern __shared__ __align__(16) uint16_t sma[];
    const int tid  = threadIdx.x;
    const int lane = tid & 31;
    const int wid  = tid >> 5;     // 0..7
    const int qt   = blockIdx.x;   // 0..7
    const int h    = blockIdx.y;
    const int b    = blockIdx.z;
    const size_t head = (size_t)b * NN * QKVC + (size_t)h * (3 * DK);
    const uint32_t sb = (uint32_t)__cvta_generic_to_shared(sma);

    // Q loader: row = tid>>1 (0..127), off = (tid&1)*32 u16 (4 chunks/plane)
    const int qrow = tid >> 1;
    const int qoff = (tid & 1) * 32;
    const uint32_t dQ = (uint32_t)(qrow * 72 + qoff) * 2;
#define AT_ISSUE_Q() do {                                                     \
        size_t r = head + (size_t)(qt * 128 + qrow) * QKVC + qoff;            \
        const uint16_t* qh_ = &g_qh[r];                                       \
        const uint16_t* ql_ = &g_ql[r];                                       \
        _Pragma("unroll")                                                     \
        for (int cc = 0; cc < 4; cc++) {                                      \
            cpa16(sb + dQ + cc * 16, qh_ + cc * 8);                           \
            cpa16(sb + dQ + A_QLO * 2 + cc * 16, ql_ + cc * 8);               \
        }                                                                     \
    } while (0)

    // KV loader: key row = tid>>2 (0..63), quarter-row 16 u16 (2 chunks/plane)
    const int lrow = tid >> 2;
    const int loff = (tid & 3) * 16;
    const uint32_t dKV = (uint32_t)(lrow * 72 + loff) * 2;
#define AT_ISSUE_KV(kt) do {                                                  \
        uint32_t st = sb + (A_ST0 + ((kt) & 1) * A_STG) * 2;                  \
        size_t r = head + (size_t)((kt) * 64 + lrow) * QKVC + loff;           \
        const uint16_t* kh_ = &g_qh[r + 64];                                  \
        const uint16_t* kl_ = &g_ql[r + 64];                                  \
        const uint16_t* vh_ = &g_qh[r + 128];                                 \
        const uint16_t* vl_ = &g_ql[r + 128];                                 \
        _Pragma("unroll")                                                     \
        for (int cc = 0; cc < 2; cc++) {                                      \
            cpa16(st + dKV + cc * 16,                kh_ + cc * 8);           \
            cpa16(st + dKV + A_KLOo * 2 + cc * 16,   kl_ + cc * 8);           \
            cpa16(st + dKV + A_VHIo * 2 + cc * 16,   vh_ + cc * 8);           \
            cpa16(st + dKV + A_VLOo * 2 + cc * 16,   vl_ + cc * 8);           \
        }                                                                     \
    } while (0)

    AT_ISSUE_Q(); AT_ISSUE_KV(0); CP_COMMIT();
    AT_ISSUE_KV(1); CP_COMMIT();

    const uint32_t kOff = ((lane & 7) + ((lane >> 4) << 3)) * 144
                        + ((lane >> 3) & 1) * 16;                 // non-trans (K)
    const uint32_t vOff = ((lane & 7) + (((lane >> 3) & 1) << 3)) * 144
                        + (lane >> 4) * 16;                        // trans (V)

    uint32_t qf[2][4][4];
    float oacc[8][4];
#pragma unroll
    for (int i = 0; i < 8; i++)
#pragma unroll
        for (int e = 0; e < 4; e++) oacc[i][e] = 0.f;
    float li0 = 0.f, li1 = 0.f;

    for (int kt = 0; kt < 16; kt++) {
        if (kt < 15) CP_WAIT1(); else CP_WAIT0();
        __syncthreads();

        if (kt == 0) {
            const uint32_t qa = sb + (wid * 16 + (lane & 15)) * 144 + (lane >> 4) * 16;
#pragma unroll
            for (int j = 0; j < 4; j++) {
                ldmx4(qa + j * 32, qf[0][j]);
                ldmx4(qa + j * 32 + A_QLO * 2, qf[1][j]);
            }
        }

        const uint32_t stb = sb + (A_ST0 + (kt & 1) * A_STG) * 2;
        const uint32_t kB = stb + kOff;
        const uint32_t vB = stb + A_VHIo * 2 + vOff;

        // ---- fused per 16-key group: S (2 n8-tiles) -> exp -> P -> PV ----
#pragma unroll
        for (int nt2 = 0; nt2 < 4; nt2++) {
            float s0[4], s1[4];
#pragma unroll
            for (int e = 0; e < 4; e++) { s0[e] = 0.f; s1[e] = 0.f; }

#pragma unroll
            for (int j = 0; j < 4; j++) {
                uint32_t kh[4], kl[4];
                uint32_t a = kB + nt2 * (16 * 144) + j * 32;
                ldmx4(a, kh);
                ldmx4(a + A_KLOo * 2, kl);
                mma_b(s0, qf[0][j], kh[0], kh[1]);
                mma_b(s0, qf[0][j], kl[0], kl[1]);
                mma_b(s0, qf[1][j], kh[0], kh[1]);
                mma_b(s1, qf[0][j], kh[2], kh[3]);
                mma_b(s1, qf[0][j], kl[2], kl[3]);
                mma_b(s1, qf[1][j], kh[2], kh[3]);
            }

#pragma unroll
            for (int e = 0; e < 4; e++) { s0[e] = ex2(s0[e]); s1[e] = ex2(s1[e]); }
            li0 += (s0[0] + s0[1]) + (s1[0] + s1[1]);
            li1 += (s0[2] + s0[3]) + (s1[2] + s1[3]);

            uint32_t ph[4], pl[4];
            ph[0] = hi2(s0[0], s0[1]); ph[1] = hi2(s0[2], s0[3]);
            ph[2] = hi2(s1[0], s1[1]); ph[3] = hi2(s1[2], s1[3]);
            pl[0] = lo2(s0[0], s0[1]); pl[1] = lo2(s0[2], s0[3]);
            pl[2] = lo2(s1[0], s1[1]); pl[3] = lo2(s1[2], s1[3]);

#pragma unroll
            for (int dt2 = 0; dt2 < 4; dt2++) {
                uint32_t vh0, vh1, vh2, vh3, vl0, vl1, vl2, vl3;
                uint32_t a = vB + nt2 * (16 * 144) + dt2 * 32;
                ldmx4t(a, vh0, vh1, vh2, vh3);
                ldmx4t(a + (A_VLOo - A_VHIo) * 2, vl0, vl1, vl2, vl3);
                mma_b(oacc[2 * dt2],     ph, vh0, vh1);
                mma_b(oacc[2 * dt2],     ph, vl0, vl1);
                mma_b(oacc[2 * dt2],     pl, vh0, vh1);
                mma_b(oacc[2 * dt2 + 1], ph, vh2, vh3);
                mma_b(oacc[2 * dt2 + 1], ph, vl2, vl3);
                mma_b(oacc[2 * dt2 + 1], pl, vh2, vh3);
            }
        }

        __syncthreads();
        if (kt + 2 < 16) { AT_ISSUE_KV(kt + 2); CP_COMMIT(); }
    }

    // ---- reduce row sums over the 4 quad lanes, normalize, write planes ----
    li0 += __shfl_xor_sync(0xffffffffu, li0, 1);
    li0 += __shfl_xor_sync(0xffffffffu, li0, 2);
    li1 += __shfl_xor_sync(0xffffffffu, li1, 1);
    li1 += __shfl_xor_sync(0xffffffffu, li1, 2);
    const float inv0 = 1.f / li0;
    const float inv1 = 1.f / li1;

    const int g   = lane >> 2;
    const int tig = lane & 3;
    const int row = qt * 128 + wid * 16 + g;
    const size_t r0 = (size_t)(b * NN + row) * CC + h * 64 + tig * 2;
    const size_t r1 = r0 + (size_t)8 * CC;
#pragma unroll
    for (int dt = 0; dt < 8; dt++) {
        float a0 = oacc[dt][0] * inv0, a1 = oacc[dt][1] * inv0;
        float a2 = oacc[dt][2] * inv1, a3 = oacc[dt][3] * inv1;
        *(uint32_t*)&g_ah[r0 + dt * 8] = hi2(a0, a1);
        *(uint32_t*)&g_al[r0 + dt * 8] = lo2(a0, a1);
        *(uint32_t*)&g_ah[r1 + dt * 8] = hi2(a2, a3);
        *(uint32_t*)&g_al[r1 + dt * 8] = lo2(a2, a3);
    }
}

// ---------------------------------------------------------------------------
// Kernel 3: out = att @ W_out + b_out + residual, tensor cores (bf16x3),
// cp.async 3-stage (R10 version); smem-transpose epilogue, bias+residual.
// ---------------------------------------------------------------------------
#define PJ_ALO    10240    // byte offsets within a stage
#define PJ_BHI    20480
#define PJ_BLO    29184
#define PJ_STAGEB 37888
#define PJ_SMEM   (3 * PJ_STAGEB)   // 113664 B

__global__ __launch_bounds__(256, 1) void k_proj(const float* __restrict__ bo,
                                                 const float* __restrict__ x,
                                                 float* __restrict__ out)
{
    extern __shared__ __align__(16) uint16_t smp[];
    const int tid  = threadIdx.x;
    const int lane = tid & 31;
    const int wid  = tid >> 5;
    const int bx   = blockIdx.x;    // bn tile 0..63
    const int by   = blockIdx.y;    // c tile 0..3
    const int b    = bx >> 3;
    const int c0   = by * 128;
    const int bn0  = bx * 128;
    const uint32_t sb = (uint32_t)__cvta_generic_to_shared(smp);

    // loader mapping
    const int am = tid >> 1;
    const int ak = (tid & 1) * 16;            // u16
    const size_t aG = (size_t)(bn0 + am) * CC + ak;
    const int bk = tid >> 3;
    const int bn = (tid & 7) * 16;            // u16
    const size_t bG = (size_t)bk * CC + c0 + bn;
    const uint32_t dAp = (uint32_t)(am * 40 + ak) * 2;
    const uint32_t dBp = PJ_BHI + (uint32_t)(bk * 136 + bn) * 2;

#define PJ_ISSUE(s) do {                                                      \
        uint32_t st = sb + ((s) % 3) * PJ_STAGEB;                             \
        const uint16_t* ah = &g_ah[aG + (s) * 32];                            \
        const uint16_t* al = &g_al[aG + (s) * 32];                            \
        const uint16_t* bh = &g_woh[bG + (size_t)(s) * 32 * CC];              \
        const uint16_t* bl = &g_wol[bG + (size_t)(s) * 32 * CC];              \
        cpa16(st + dAp, ah);                cpa16(st + dAp + 16, ah + 8);     \
        cpa16(st + dAp + PJ_ALO, al);       cpa16(st + dAp + PJ_ALO + 16, al + 8); \
        cpa16(st + dBp, bh);                cpa16(st + dBp + 16, bh + 8);     \
        cpa16(st + dBp + 8704, bl);         cpa16(st + dBp + 8704 + 16, bl + 8); \
    } while (0)

    const int wm = wid >> 2;
    const int wn = wid & 3;
    const uint32_t aOff = (wm * 64 + (lane & 15)) * 80 + (lane >> 4) * 16;
    const uint32_t bOff = PJ_BHI + ((lane & 7) + (((lane >> 3) & 1) << 3)) * 272
                        + (uint32_t)(wn * 64) + (lane >> 4) * 16;

    float acc[4][4][4];
#pragma unroll
    for (int i = 0; i < 4; i++)
#pragma unroll
        for (int j = 0; j < 4; j++)
#pragma unroll
            for (int e = 0; e < 4; e++) acc[i][j][e] = 0.f;

    PJ_ISSUE(0); CP_COMMIT();
    PJ_ISSUE(1); CP_COMMIT();

    for (int s = 0; s < 16; s++) {
        if (s < 15) CP_WAIT1(); else CP_WAIT0();
        __syncthreads();
        if (s + 2 < 16) { PJ_ISSUE(s + 2); CP_COMMIT(); }

        const uint32_t base = sb + (uint32_t)(s % 3) * PJ_STAGEB;
#pragma unroll
        for (int ks = 0; ks < 2; ks++) {
            uint32_t ahi[4][4], alo[4][4], bhi[4][2], blo[4][2];
#pragma unroll
            for (int i = 0; i < 4; i++) {
                uint32_t a = base + aOff + i * (16 * 80) + ks * 32;
                ldmx4(a, ahi[i]);
                ldmx4(a + PJ_ALO, alo[i]);
            }
#pragma unroll
            for (int j2 = 0; j2 < 2; j2++) {
                uint32_t a = base + bOff + ks * 4352 + j2 * 32;
                ldmx4t(a, bhi[2 * j2][0], bhi[2 * j2][1], bhi[2 * j2 + 1][0], bhi[2 * j2 + 1][1]);
                ldmx4t(a + 8704, blo[2 * j2][0], blo[2 * j2][1], blo[2 * j2 + 1][0], blo[2 * j2 + 1][1]);
            }
#pragma unroll
            for (int i = 0; i < 4; i++)
#pragma unroll
                for (int jn = 0; jn < 4; jn++) {
                    mma16816(acc[i][jn], ahi[i], bhi[jn]);
                    mma16816(acc[i][jn], ahi[i], blo[jn]);
                    mma16816(acc[i][jn], alo[i], bhi[jn]);
                }
        }
    }

    // ---- epilogue: transpose via smem, fused bias + residual ----
    __syncthreads();
    float* S = (float*)smp;   // [128 c][stride 132] of m
    const int g   = lane >> 2;
    const int tig = lane & 3;
#pragma unroll
    for (int i = 0; i < 4; i++) {
        int m_l = wm * 64 + i * 16 + g;
#pragma unroll
        for (int jn = 0; jn < 4; jn++) {
            int c_l = wn * 32 + jn * 8 + tig * 2;
            S[c_l * 132 + m_l]           = acc[i][jn][0];
            S[(c_l + 1) * 132 + m_l]     = acc[i][jn][1];
            S[c_l * 132 + m_l + 8]       = acc[i][jn][2];
            S[(c_l + 1) * 132 + m_l + 8] = acc[i][jn][3];
        }
    }
    __syncthreads();
    {
        const int c_l  = tid >> 1;
        const int mseg = (tid & 1) * 64;
        const int c    = c0 + c_l;
        const float bias = bo[c];
        const int n0 = (bx & 7) * 128;
        const size_t basep = (size_t)b * CC * NN + (size_t)c * NN + n0 + mseg;
#pragma unroll
        for (int i = 0; i < 16; i++) {
            float4 v  = *(float4*)&S[c_l * 132 + mseg + 4 * i];
            float4 xr = *(const float4*)&x[basep + 4 * i];
            v.x += bias + xr.x; v.y += bias + xr.y;
            v.z += bias + xr.z; v.w += bias + xr.w;
            *(float4*)&out[basep + 4 * i] = v;
        }
    }
}

// ---------------------------------------------------------------------------
extern "C" void kernel_launch(void* const* d_in, const int* in_sizes, int n_in,
                              void* d_out, int out_size)
{
    const float* x  = (const float*)d_in[0];
    const float* Wq = (const float*)d_in[1];
    const float* bq = (const float*)d_in[2];
    const float* Wo = (const float*)d_in[3];
    const float* bo = (const float*)d_in[4];
    float* out = (float*)d_out;

    k_cvt<<<(BB * CC * NN / 4 + 255) / 256, 256>>>(x, 0, BB * CC * NN / 4);
    k_cvt<<<(CC * QKVC / 4 + 255) / 256, 256>>>(Wq, 1, CC * QKVC / 4);
    k_cvt<<<(CC * CC / 4 + 255) / 256, 256>>>(Wo, 2, CC * CC / 4);

    cudaFuncSetAttribute(k_qkv, cudaFuncAttributeMaxDynamicSharedMemorySize, QK_SMEM);
    k_qkv<<<dim3(12, 64), 256, QK_SMEM>>>(bq);

    cudaFuncSetAttribute(k_attn, cudaFuncAttributeMaxDynamicSharedMemorySize, A_SMEM_BYTES);
    k_attn<<<dim3(8, HEADS, BB), 256, A_SMEM_BYTES>>>();

    cudaFuncSetAttribute(k_proj, cudaFuncAttributeMaxDynamicSharedMemorySize, PJ_SMEM);
    k_proj<<<dim3(64, 4), 256, PJ_SMEM>>>(bo, x, out);
}

// round 15
// speedup vs baseline: 1.5381x; 1.3333x over previous
#include <cuda_runtime.h>
#include <math.h>
#include <stdint.h>

// Problem constants
#define BB    8
#define CC    512
#define NN    1024        // H*W = 32*32
#define HEADS 8
#define DK    64
#define QKVC  1536        // HEADS * DK * 3
#define SCL2E 0.18033688f // DK^-0.5 * log2(e)

// ---------------------------------------------------------------------------
// Scratch (device globals; no allocation allowed) — fp16 hi/lo planes
// ---------------------------------------------------------------------------
__device__ uint16_t g_xh[BB * CC * NN],  g_xl[BB * CC * NN];    // x split
__device__ uint16_t g_wqh[CC * QKVC];                           // W_qkv hi
__device__ uint16_t g_woh[CC * CC];                             // W_out hi
__device__ uint16_t g_qh[BB * NN * QKVC], g_ql[BB * NN * QKVC]; // qkv (Q pre-scaled)
__device__ uint16_t g_ah[BB * NN * CC],  g_al[BB * NN * CC];    // attention out

// ---------------------------------------------------------------------------
// Helpers (fp16 split: f = hi + lo, hi = rn(f), lo = rn(f - hi))
// ---------------------------------------------------------------------------
__device__ __forceinline__ float ex2(float x) {
    float y;
    asm("ex2.approx.f32 %0, %1;" : "=f"(y) : "f"(x));
    return y;
}
__device__ __forceinline__ uint32_t hi2(float f0, float f1) {   // {f16(f0)|f16(f1)<<16}
    uint32_t r;
    asm("cvt.rn.f16x2.f32 %0, %1, %2;" : "=r"(r) : "f"(f1), "f"(f0));
    return r;
}
__device__ __forceinline__ uint32_t lo2(float f0, float f1) {
    uint32_t h = hi2(f0, f1);
    float g0, g1;
    asm("{\n\t.reg .b16 x, y;\n\tmov.b32 {x, y}, %2;\n\t"
        "cvt.f32.f16 %0, x;\n\tcvt.f32.f16 %1, y;\n\t}"
        : "=f"(g0), "=f"(g1) : "r"(h));
    return hi2(f0 - g0, f1 - g1);
}

__device__ __forceinline__ void cpa16(uint32_t dst, const void* src) {
    asm volatile("cp.async.cg.shared.global [%0], [%1], 16;" :: "r"(dst), "l"(src));
}
#define CP_COMMIT() asm volatile("cp.async.commit_group;" ::: "memory")
#define CP_WAIT1()  asm volatile("cp.async.wait_group 1;" ::: "memory")
#define CP_WAIT0()  asm volatile("cp.async.wait_group 0;" ::: "memory")

__device__ __forceinline__ void ldmx4t(uint32_t addr, uint32_t& r0, uint32_t& r1,
                                       uint32_t& r2, uint32_t& r3) {
    asm volatile("ldmatrix.sync.aligned.m8n8.x4.trans.shared.b16 {%0,%1,%2,%3}, [%4];"
                 : "=r"(r0), "=r"(r1), "=r"(r2), "=r"(r3) : "r"(addr));
}
__device__ __forceinline__ void ldmx4(uint32_t addr, uint32_t* r) {
    asm volatile("ldmatrix.sync.aligned.m8n8.x4.shared.b16 {%0,%1,%2,%3}, [%4];"
                 : "=r"(r[0]), "=r"(r[1]), "=r"(r[2]), "=r"(r[3]) : "r"(addr));
}
__device__ __forceinline__ void mma16816(float* d, const uint32_t* a, const uint32_t* b) {
    asm volatile("mma.sync.aligned.m16n8k16.row.col.f32.f16.f16.f32 "
                 "{%0,%1,%2,%3}, {%4,%5,%6,%7}, {%8,%9}, {%0,%1,%2,%3};"
                 : "+f"(d[0]), "+f"(d[1]), "+f"(d[2]), "+f"(d[3])
                 : "r"(a[0]), "r"(a[1]), "r"(a[2]), "r"(a[3]), "r"(b[0]), "r"(b[1]));
}
__device__ __forceinline__ void mma_b(float* d, const uint32_t* a, uint32_t b0, uint32_t b1) {
    asm volatile("mma.sync.aligned.m16n8k16.row.col.f32.f16.f16.f32 "
                 "{%0,%1,%2,%3}, {%4,%5,%6,%7}, {%8,%9}, {%0,%1,%2,%3};"
                 : "+f"(d[0]), "+f"(d[1]), "+f"(d[2]), "+f"(d[3])
                 : "r"(a[0]), "r"(a[1]), "r"(a[2]), "r"(a[3]), "r"(b0), "r"(b1));
}

// ---------------------------------------------------------------------------
// Kernel 0: fp32 -> fp16 plane split (pre-pass)
// which 0: x (hi+lo), 1: Wq (hi only), 2: Wo (hi only)
// ---------------------------------------------------------------------------
__global__ __launch_bounds__(256) void k_cvt(const float* __restrict__ src,
                                             int which, int n4)
{
    int i = blockIdx.x * blockDim.x + threadIdx.x;
    if (i >= n4) return;
    float4 v = ((const float4*)src)[i];
    uint2 h = make_uint2(hi2(v.x, v.y), hi2(v.z, v.w));
    if (which == 0) {
        ((uint2*)g_xh)[i] = h;
        ((uint2*)g_xl)[i] = make_uint2(lo2(v.x, v.y), lo2(v.z, v.w));
    } else if (which == 1) {
        ((uint2*)g_wqh)[i] = h;
    } else {
        ((uint2*)g_woh)[i] = h;
    }
}

// ---------------------------------------------------------------------------
// Kernel 1: QKV GEMM, tensor cores (fp16, A split x2, B hi), cp.async
// 3-stage, 8 warps, warp tile 64x32. Output fp16 hi/lo planes, Q pre-scaled.
// Stage planes: Ah, Al, Wh (each 32 k-rows x 128 u16, row stride 272B).
// ---------------------------------------------------------------------------
#define KBYTES  8704            // one plane: 32 * 272 B
#define QK_STG  (3 * KBYTES)    // 26112 B per stage
#define QK_SMEM (3 * QK_STG)    // 78336 B

__global__ __launch_bounds__(256) void k_qkv(const float* __restrict__ bq)
{
    extern __shared__ __align__(16) uint16_t smq[];
    const int tid  = threadIdx.x;
    const int lane = tid & 31;
    const int wid  = tid >> 5;
    const int bx   = blockIdx.x;          // c tile 0..11
    const int by   = blockIdx.y;          // m tile 0..63
    const int b    = by >> 3;
    const int n0   = (by & 7) << 7;
    const int c0   = bx * 128;
    const uint32_t sbase = (uint32_t)__cvta_generic_to_shared(smq);

    // loader mapping: row lk (0..31), 16 u16 (32B) per plane per matrix
    const int lk  = tid >> 3;
    const int lmf = (tid & 7) * 16;
    const size_t aG = (size_t)b * CC * NN + n0 + lmf + (size_t)lk * NN;
    const size_t wG = (size_t)c0 + lmf + (size_t)lk * QKVC;
    const uint32_t dA = (uint32_t)(lk * 136 + lmf) * 2;

    const int wm = wid >> 2;
    const int wn = wid & 3;
    const uint32_t aOff = ((lane & 7) + ((lane >> 4) << 3)) * 272
                        + (uint32_t)(wm * 128) + ((lane >> 3) & 1) * 16;
    const uint32_t bOff = ((lane & 7) + (((lane >> 3) & 1) << 3)) * 272
                        + (uint32_t)(wn * 64) + (lane >> 4) * 16;

    float acc[4][4][4];
#pragma unroll
    for (int i = 0; i < 4; i++)
#pragma unroll
        for (int j = 0; j < 4; j++)
#pragma unroll
            for (int e = 0; e < 4; e++) acc[i][j][e] = 0.f;

#define QK_ISSUE(s) do {                                                      \
        uint32_t st = sbase + ((s) % 3) * QK_STG;                             \
        size_t ko = (size_t)(s) * 32;                                         \
        const uint16_t* ah = &g_xh[aG + ko * NN];                             \
        const uint16_t* al = &g_xl[aG + ko * NN];                             \
        const uint16_t* wh = &g_wqh[wG + ko * QKVC];                          \
        cpa16(st + dA, ah);                   cpa16(st + dA + 16, ah + 8);    \
        cpa16(st + dA + KBYTES, al);          cpa16(st + dA + KBYTES + 16, al + 8); \
        cpa16(st + dA + 2 * KBYTES, wh);      cpa16(st + dA + 2 * KBYTES + 16, wh + 8); \
    } while (0)

    QK_ISSUE(0); CP_COMMIT();
    QK_ISSUE(1); CP_COMMIT();

    for (int s = 0; s < 16; s++) {
        if (s < 15) CP_WAIT1(); else CP_WAIT0();
        __syncthreads();
        if (s + 2 < 16) { QK_ISSUE(s + 2); CP_COMMIT(); }

        const uint32_t base = sbase + (uint32_t)(s % 3) * QK_STG;
#pragma unroll
        for (int ks = 0; ks < 2; ks++) {
            uint32_t ahi[4][4], alo[4][4], bhi[4][2];
#pragma unroll
            for (int i = 0; i < 4; i++) {
                uint32_t addr = base + aOff + ks * 4352 + i * 32;
                ldmx4t(addr, ahi[i][0], ahi[i][1], ahi[i][2], ahi[i][3]);
                ldmx4t(addr + KBYTES, alo[i][0], alo[i][1], alo[i][2], alo[i][3]);
            }
#pragma unroll
            for (int j2 = 0; j2 < 2; j2++) {
                uint32_t addr = base + 2 * KBYTES + bOff + ks * 4352 + j2 * 32;
                ldmx4t(addr, bhi[2 * j2][0], bhi[2 * j2][1], bhi[2 * j2 + 1][0], bhi[2 * j2 + 1][1]);
            }
#pragma unroll
            for (int i = 0; i < 4; i++)
#pragma unroll
                for (int jn = 0; jn < 4; jn++) {
                    mma16816(acc[i][jn], ahi[i], bhi[jn]);
                    mma16816(acc[i][jn], alo[i], bhi[jn]);
                }
        }
    }

    // ---- epilogue: bias, pre-scale Q columns, split hi/lo ----
    const int g   = lane >> 2;
    const int tig = lane & 3;
#pragma unroll
    for (int i = 0; i < 4; i++) {
        int m = by * 128 + wm * 64 + i * 16 + g;
#pragma unroll
        for (int jn = 0; jn < 4; jn++) {
            int c = c0 + wn * 32 + jn * 8 + tig * 2;
            float2 bias = *(const float2*)&bq[c];
            float sc = ((c % 192) < 64) ? SCL2E : 1.f;
            float v0 = (acc[i][jn][0] + bias.x) * sc;
            float v1 = (acc[i][jn][1] + bias.y) * sc;
            float v2 = (acc[i][jn][2] + bias.x) * sc;
            float v3 = (acc[i][jn][3] + bias.y) * sc;
            size_t i0 = (size_t)m * QKVC + c;
            size_t i1 = (size_t)(m + 8) * QKVC + c;
            *(uint32_t*)&g_qh[i0] = hi2(v0, v1);
            *(uint32_t*)&g_ql[i0] = lo2(v0, v1);
            *(uint32_t*)&g_qh[i1] = hi2(v2, v3);
            *(uint32_t*)&g_ql[i1] = lo2(v2, v3);
        }
    }
}

// ---------------------------------------------------------------------------
// Kernel 2: attention, tensor cores (fp16; Q split x2, K/V hi only),
// 8 warps x 16 q-rows, K/V stages of 64 keys double-buffered.
// Smem: Qh, Ql (128x72 u16 each) + 2 stages of {Kh, Vh} (64x72 each) = 73728 B.
// ---------------------------------------------------------------------------
#define A_QLO   9216            // u16 offsets
#define A_ST0   18432           // stage region start (u16)
#define A_STG   9216            // u16 per stage (2 planes * 64*72)
#define A_VHIo  4608            // V hi within stage (u16)
#define A_SMEM_BYTES ((A_ST0 + 2 * A_STG) * 2)   // 73728 B

__global__ __launch_bounds__(256, 2) void k_attn()
{
    extern __shared__ __align__(16) uint16_t sma[];
    const int tid  = threadIdx.x;
    const int lane = tid & 31;
    const int wid  = tid >> 5;     // 0..7
    const int qt   = blockIdx.x;   // 0..7
    const int h    = blockIdx.y;
    const int b    = blockIdx.z;
    const size_t head = (size_t)b * NN * QKVC + (size_t)h * (3 * DK);
    const uint32_t sb = (uint32_t)__cvta_generic_to_shared(sma);

    // Q loader: row = tid>>1 (0..127), off = (tid&1)*32 u16 (4 chunks/plane)
    const int qrow = tid >> 1;
    const int qoff = (tid & 1) * 32;
    const uint32_t dQ = (uint32_t)(qrow * 72 + qoff) * 2;
#define AT_ISSUE_Q() do {                                                     \
        size_t rr = head + (size_t)(qt * 128 + qrow) * QKVC + qoff;           \
        const uint16_t* qh_ = &g_qh[rr];                                      \
        const uint16_t* ql_ = &g_ql[rr];                                      \
        _Pragma("unroll")                                                     \
        for (int cc = 0; cc < 4; cc++) {                                      \
            cpa16(sb + dQ + cc * 16, qh_ + cc * 8);                           \
            cpa16(sb + dQ + A_QLO * 2 + cc * 16, ql_ + cc * 8);               \
        }                                                                     \
    } while (0)

    // KV loader: key row = tid>>2 (0..63), quarter-row 16 u16 (2 chunks/plane)
    const int lrow = tid >> 2;
    const int loff = (tid & 3) * 16;
    const uint32_t dKV = (uint32_t)(lrow * 72 + loff) * 2;
#define AT_ISSUE_KV(kt) do {                                                  \
        uint32_t st = sb + (A_ST0 + ((kt) & 1) * A_STG) * 2;                  \
        size_t rr = head + (size_t)((kt) * 64 + lrow) * QKVC + loff;          \
        const uint16_t* kh_ = &g_qh[rr + 64];                                 \
        const uint16_t* vh_ = &g_qh[rr + 128];                                \
        _Pragma("unroll")                                                     \
        for (int cc = 0; cc < 2; cc++) {                                      \
            cpa16(st + dKV + cc * 16,              kh_ + cc * 8);             \
            cpa16(st + dKV + A_VHIo * 2 + cc * 16, vh_ + cc * 8);             \
        }                                                                     \
    } while (0)

    AT_ISSUE_Q(); AT_ISSUE_KV(0); CP_COMMIT();
    AT_ISSUE_KV(1); CP_COMMIT();

    const uint32_t kOff = ((lane & 7) + ((lane >> 4) << 3)) * 144
                        + ((lane >> 3) & 1) * 16;                 // non-trans (K)
    const uint32_t vOff = ((lane & 7) + (((lane >> 3) & 1) << 3)) * 144
                        + (lane >> 4) * 16;                        // trans (V)

    uint32_t qf[2][4][4];
    float oacc[8][4];
#pragma unroll
    for (int i = 0; i < 8; i++)
#pragma unroll
        for (int e = 0; e < 4; e++) oacc[i][e] = 0.f;
    float li0 = 0.f, li1 = 0.f;

    for (int kt = 0; kt < 16; kt++) {
        if (kt < 15) CP_WAIT1(); else CP_WAIT0();
        __syncthreads();

        if (kt == 0) {
            const uint32_t qa = sb + (wid * 16 + (lane & 15)) * 144 + (lane >> 4) * 16;
#pragma unroll
            for (int j = 0; j < 4; j++) {
                ldmx4(qa + j * 32, qf[0][j]);
                ldmx4(qa + j * 32 + A_QLO * 2, qf[1][j]);
            }
        }

        const uint32_t stb = sb + (A_ST0 + (kt & 1) * A_STG) * 2;
        const uint32_t kB = stb + kOff;
        const uint32_t vB = stb + A_VHIo * 2 + vOff;

        // ---- fused per 16-key group: S (2 n8-tiles) -> exp -> P -> PV ----
#pragma unroll
        for (int nt2 = 0; nt2 < 4; nt2++) {
            float s0[4], s1[4];
#pragma unroll
            for (int e = 0; e < 4; e++) { s0[e] = 0.f; s1[e] = 0.f; }

#pragma unroll
            for (int j = 0; j < 4; j++) {
                uint32_t kh[4];
                uint32_t a = kB + nt2 * (16 * 144) + j * 32;
                ldmx4(a, kh);
                mma_b(s0, qf[0][j], kh[0], kh[1]);
                mma_b(s0, qf[1][j], kh[0], kh[1]);
                mma_b(s1, qf[0][j], kh[2], kh[3]);
                mma_b(s1, qf[1][j], kh[2], kh[3]);
            }

#pragma unroll
            for (int e = 0; e < 4; e++) { s0[e] = ex2(s0[e]); s1[e] = ex2(s1[e]); }
            li0 += (s0[0] + s0[1]) + (s1[0] + s1[1]);
            li1 += (s0[2] + s0[3]) + (s1[2] + s1[3]);

            uint32_t ph[4], pl[4];
            ph[0] = hi2(s0[0], s0[1]); ph[1] = hi2(s0[2], s0[3]);
            ph[2] = hi2(s1[0], s1[1]); ph[3] = hi2(s1[2], s1[3]);
            pl[0] = lo2(s0[0], s0[1]); pl[1] = lo2(s0[2], s0[3]);
            pl[2] = lo2(s1[0], s1[1]); pl[3] = lo2(s1[2], s1[3]);

#pragma unroll
            for (int dt2 = 0; dt2 < 4; dt2++) {
                uint32_t vh0, vh1, vh2, vh3;
                uint32_t a = vB + nt2 * (16 * 144) + dt2 * 32;
                ldmx4t(a, vh0, vh1, vh2, vh3);
                mma_b(oacc[2 * dt2],     ph, vh0, vh1);
                mma_b(oacc[2 * dt2],     pl, vh0, vh1);
                mma_b(oacc[2 * dt2 + 1], ph, vh2, vh3);
                mma_b(oacc[2 * dt2 + 1], pl, vh2, vh3);
            }
        }

        __syncthreads();
        if (kt + 2 < 16) { AT_ISSUE_KV(kt + 2); CP_COMMIT(); }
    }

    // ---- reduce row sums over the 4 quad lanes, normalize, write planes ----
    li0 += __shfl_xor_sync(0xffffffffu, li0, 1);
    li0 += __shfl_xor_sync(0xffffffffu, li0, 2);
    li1 += __shfl_xor_sync(0xffffffffu, li1, 1);
    li1 += __shfl_xor_sync(0xffffffffu, li1, 2);
    const float inv0 = 1.f / li0;
    const float inv1 = 1.f / li1;

    const int g   = lane >> 2;
    const int tig = lane & 3;
    const int row = qt * 128 + wid * 16 + g;
    const size_t r0 = (size_t)(b * NN + row) * CC + h * 64 + tig * 2;
    const size_t r1 = r0 + (size_t)8 * CC;
#pragma unroll
    for (int dt = 0; dt < 8; dt++) {
        float a0 = oacc[dt][0] * inv0, a1 = oacc[dt][1] * inv0;
        float a2 = oacc[dt][2] * inv1, a3 = oacc[dt][3] * inv1;
        *(uint32_t*)&g_ah[r0 + dt * 8] = hi2(a0, a1);
        *(uint32_t*)&g_al[r0 + dt * 8] = lo2(a0, a1);
        *(uint32_t*)&g_ah[r1 + dt * 8] = hi2(a2, a3);
        *(uint32_t*)&g_al[r1 + dt * 8] = lo2(a2, a3);
    }
}

// ---------------------------------------------------------------------------
// Kernel 3: out = att @ W_out + b_out + residual (fp16; A split x2, B hi),
// cp.async 3-stage; smem-transpose epilogue with fused bias+residual.
// Stage planes: Ah (128x40 u16), Al, Bh (32x136 u16).
// ---------------------------------------------------------------------------
#define PJ_ALO    10240    // byte offsets within a stage
#define PJ_BHI    20480
#define PJ_STAGEB 29184    // 20480 + 8704
#define PJ_SMEM   (3 * PJ_STAGEB)   // 87552 B

__global__ __launch_bounds__(256, 1) void k_proj(const float* __restrict__ bo,
                                                 const float* __restrict__ x,
                                                 float* __restrict__ out)
{
    extern __shared__ __align__(16) uint16_t smp[];
    const int tid  = threadIdx.x;
    const int lane = tid & 31;
    const int wid  = tid >> 5;
    const int bx   = blockIdx.x;    // bn tile 0..63
    const int by   = blockIdx.y;    // c tile 0..3
    const int b    = bx >> 3;
    const int c0   = by * 128;
    const int bn0  = bx * 128;
    const uint32_t sb = (uint32_t)__cvta_generic_to_shared(smp);

    // loader mapping
    const int am = tid >> 1;
    const int ak = (tid & 1) * 16;            // u16
    const size_t aG = (size_t)(bn0 + am) * CC + ak;
    const int bk = tid >> 3;
    const int bn = (tid & 7) * 16;            // u16
    const size_t bG = (size_t)bk * CC + c0 + bn;
    const uint32_t dAp = (uint32_t)(am * 40 + ak) * 2;
    const uint32_t dBp = PJ_BHI + (uint32_t)(bk * 136 + bn) * 2;

#define PJ_ISSUE(s) do {                                                      \
        uint32_t st = sb + ((s) % 3) * PJ_STAGEB;                             \
        const uint16_t* ah = &g_ah[aG + (s) * 32];                            \
        const uint16_t* al = &g_al[aG + (s) * 32];                            \
        const uint16_t* bh = &g_woh[bG + (size_t)(s) * 32 * CC];              \
        cpa16(st + dAp, ah);                cpa16(st + dAp + 16, ah + 8);     \
        cpa16(st + dAp + PJ_ALO, al);       cpa16(st + dAp + PJ_ALO + 16, al + 8); \
        cpa16(st + dBp, bh);                cpa16(st + dBp + 16, bh + 8);     \
    } while (0)

    const int wm = wid >> 2;
    const int wn = wid & 3;
    const uint32_t aOff = (wm * 64 + (lane & 15)) * 80 + (lane >> 4) * 16;
    const uint32_t bOff = PJ_BHI + ((lane & 7) + (((lane >> 3) & 1) << 3)) * 272
                        + (uint32_t)(wn * 64) + (lane >> 4) * 16;

    float acc[4][4][4];
#pragma unroll
    for (int i = 0; i < 4; i++)
#pragma unroll
        for (int j = 0; j < 4; j++)
#pragma unroll
            for (int e = 0; e < 4; e++) acc[i][j][e] = 0.f;

    PJ_ISSUE(0); CP_COMMIT();
    PJ_ISSUE(1); CP_COMMIT();

    for (int s = 0; s < 16; s++) {
        if (s < 15) CP_WAIT1(); else CP_WAIT0();
        __syncthreads();
        if (s + 2 < 16) { PJ_ISSUE(s + 2); CP_COMMIT(); }

        const uint32_t base = sb + (uint32_t)(s % 3) * PJ_STAGEB;
#pragma unroll
        for (int ks = 0; ks < 2; ks++) {
            uint32_t ahi[4][4], alo[4][4], bhi[4][2];
#pragma unroll
            for (int i = 0; i < 4; i++) {
                uint32_t a = base + aOff + i * (16 * 80) + ks * 32;
                ldmx4(a, ahi[i]);
                ldmx4(a + PJ_ALO, alo[i]);
            }
#pragma unroll
            for (int j2 = 0; j2 < 2; j2++) {
                uint32_t a = base + bOff + ks * 4352 + j2 * 32;
                ldmx4t(a, bhi[2 * j2][0], bhi[2 * j2][1], bhi[2 * j2 + 1][0], bhi[2 * j2 + 1][1]);
            }
#pragma unroll
            for (int i = 0; i < 4; i++)
#pragma unroll
                for (int jn = 0; jn < 4; jn++) {
                    mma16816(acc[i][jn], ahi[i], bhi[jn]);
                    mma16816(acc[i][jn], alo[i], bhi[jn]);
                }
        }
    }

    // ---- epilogue: transpose via smem, fused bias + residual ----
    __syncthreads();
    float* S = (float*)smp;   // [128 c][stride 132] of m
    const int g   = lane >> 2;
    const int tig = lane & 3;
#pragma unroll
    for (int i = 0; i < 4; i++) {
        int m_l = wm * 64 + i * 16 + g;
#pragma unroll
        for (int jn = 0; jn < 4; jn++) {
            int c_l = wn * 32 + jn * 8 + tig * 2;
            S[c_l * 132 + m_l]           = acc[i][jn][0];
            S[(c_l + 1) * 132 + m_l]     = acc[i][jn][1];
            S[c_l * 132 + m_l + 8]       = acc[i][jn][2];
            S[(c_l + 1) * 132 + m_l + 8] = acc[i][jn][3];
        }
    }
    __syncthreads();
    {
        const int c_l  = tid >> 1;
        const int mseg = (tid & 1) * 64;
        const int c    = c0 + c_l;
        const float bias = bo[c];
        const int n0 = (bx & 7) * 128;
        const size_t basep = (size_t)b * CC * NN + (size_t)c * NN + n0 + mseg;
#pragma unroll
        for (int i = 0; i < 16; i++) {
            float4 v  = *(float4*)&S[c_l * 132 + mseg + 4 * i];
            float4 xr = *(const float4*)&x[basep + 4 * i];
            v.x += bias + xr.x; v.y += bias + xr.y;
            v.z += bias + xr.z; v.w += bias + xr.w;
            *(float4*)&out[basep + 4 * i] = v;
        }
    }
}

// ---------------------------------------------------------------------------
extern "C" void kernel_launch(void* const* d_in, const int* in_sizes, int n_in,
                              void* d_out, int out_size)
{
    const float* x  = (const float*)d_in[0];
    const float* Wq = (const float*)d_in[1];
    const float* bq = (const float*)d_in[2];
    const float* Wo = (const float*)d_in[3];
    const float* bo = (const float*)d_in[4];
    float* out = (float*)d_out;

    k_cvt<<<(BB * CC * NN / 4 + 255) / 256, 256>>>(x, 0, BB * CC * NN / 4);
    k_cvt<<<(CC * QKVC / 4 + 255) / 256, 256>>>(Wq, 1, CC * QKVC / 4);
    k_cvt<<<(CC * CC / 4 + 255) / 256, 256>>>(Wo, 2, CC * CC / 4);

    cudaFuncSetAttribute(k_qkv, cudaFuncAttributeMaxDynamicSharedMemorySize, QK_SMEM);
    k_qkv<<<dim3(12, 64), 256, QK_SMEM>>>(bq);

    cudaFuncSetAttribute(k_attn, cudaFuncAttributeMaxDynamicSharedMemorySize, A_SMEM_BYTES);
    k_attn<<<dim3(8, HEADS, BB), 256, A_SMEM_BYTES>>>();

    cudaFuncSetAttribute(k_proj, cudaFuncAttributeMaxDynamicSharedMemorySize, PJ_SMEM);
    k_proj<<<dim3(64, 4), 256, PJ_SMEM>>>(bo, x, out);
}

// round 16
// speedup vs baseline: 2.6569x; 1.7274x over previous
#include <cuda_runtime.h>
#include <math.h>
#include <stdint.h>

// Problem constants
#define BB    8
#define CC    512
#define NN    1024        // H*W = 32*32
#define HEADS 8
#define DK    64
#define QKVC  1536        // HEADS * DK * 3
#define SCL2E 0.18033688f // DK^-0.5 * log2(e)

// ---------------------------------------------------------------------------
// Scratch (device globals; no allocation allowed) — fp16 planes
// ---------------------------------------------------------------------------
__device__ uint16_t g_xh[BB * CC * NN];                          // x fp16
__device__ uint16_t g_wqh[CC * QKVC];                            // W_qkv fp16
__device__ uint16_t g_woh[CC * CC];                              // W_out fp16
__device__ uint16_t g_qh[BB * NN * QKVC];                        // qkv (Q pre-scaled)
__device__ uint16_t g_ah[BB * NN * CC];                          // attention out

// ---------------------------------------------------------------------------
// Helpers
// ---------------------------------------------------------------------------
__device__ __forceinline__ float ex2(float x) {
    float y;
    asm("ex2.approx.f32 %0, %1;" : "=f"(y) : "f"(x));
    return y;
}
__device__ __forceinline__ uint32_t hi2(float f0, float f1) {   // {f16(f0)|f16(f1)<<16}
    uint32_t r;
    asm("cvt.rn.f16x2.f32 %0, %1, %2;" : "=r"(r) : "f"(f1), "f"(f0));
    return r;
}

__device__ __forceinline__ void cpa16(uint32_t dst, const void* src) {
    asm volatile("cp.async.cg.shared.global [%0], [%1], 16;" :: "r"(dst), "l"(src));
}
#define CP_COMMIT() asm volatile("cp.async.commit_group;" ::: "memory")
#define CP_WAIT1()  asm volatile("cp.async.wait_group 1;" ::: "memory")
#define CP_WAIT0()  asm volatile("cp.async.wait_group 0;" ::: "memory")

__device__ __forceinline__ void ldmx4t(uint32_t addr, uint32_t& r0, uint32_t& r1,
                                       uint32_t& r2, uint32_t& r3) {
    asm volatile("ldmatrix.sync.aligned.m8n8.x4.trans.shared.b16 {%0,%1,%2,%3}, [%4];"
                 : "=r"(r0), "=r"(r1), "=r"(r2), "=r"(r3) : "r"(addr));
}
__device__ __forceinline__ void ldmx4(uint32_t addr, uint32_t* r) {
    asm volatile("ldmatrix.sync.aligned.m8n8.x4.shared.b16 {%0,%1,%2,%3}, [%4];"
                 : "=r"(r[0]), "=r"(r[1]), "=r"(r[2]), "=r"(r[3]) : "r"(addr));
}
__device__ __forceinline__ void mma16816(float* d, const uint32_t* a, const uint32_t* b) {
    asm volatile("mma.sync.aligned.m16n8k16.row.col.f32.f16.f16.f32 "
                 "{%0,%1,%2,%3}, {%4,%5,%6,%7}, {%8,%9}, {%0,%1,%2,%3};"
                 : "+f"(d[0]), "+f"(d[1]), "+f"(d[2]), "+f"(d[3])
                 : "r"(a[0]), "r"(a[1]), "r"(a[2]), "r"(a[3]), "r"(b[0]), "r"(b[1]));
}
__device__ __forceinline__ void mma_b(float* d, const uint32_t* a, uint32_t b0, uint32_t b1) {
    asm volatile("mma.sync.aligned.m16n8k16.row.col.f32.f16.f16.f32 "
                 "{%0,%1,%2,%3}, {%4,%5,%6,%7}, {%8,%9}, {%0,%1,%2,%3};"
                 : "+f"(d[0]), "+f"(d[1]), "+f"(d[2]), "+f"(d[3])
                 : "r"(a[0]), "r"(a[1]), "r"(a[2]), "r"(a[3]), "r"(b0), "r"(b1));
}

// ---------------------------------------------------------------------------
// Kernel 0: fp32 -> fp16 plane (pre-pass).  which 0: x, 1: Wq, 2: Wo
// ---------------------------------------------------------------------------
__global__ __launch_bounds__(256) void k_cvt(const float* __restrict__ src,
                                             int which, int n4)
{
    int i = blockIdx.x * blockDim.x + threadIdx.x;
    if (i >= n4) return;
    float4 v = ((const float4*)src)[i];
    uint2 h = make_uint2(hi2(v.x, v.y), hi2(v.z, v.w));
    if (which == 0)      ((uint2*)g_xh)[i]  = h;
    else if (which == 1) ((uint2*)g_wqh)[i] = h;
    else                 ((uint2*)g_woh)[i] = h;
}

// ---------------------------------------------------------------------------
// Kernel 1: QKV GEMM, tensor cores (fp16), cp.async 3-stage, 8 warps,
// warp tile 64x32.  Output fp16 plane, Q pre-scaled.
// Stage planes: Ah, Wh (each 32 k-rows x 128 u16, row stride 272B).
// ---------------------------------------------------------------------------
#define KBYTES  8704            // one plane: 32 * 272 B
#define QK_STG  (2 * KBYTES)    // 17408 B per stage
#define QK_SMEM (3 * QK_STG)    // 52224 B

__global__ __launch_bounds__(256) void k_qkv(const float* __restrict__ bq)
{
    extern __shared__ __align__(16) uint16_t smq[];
    const int tid  = threadIdx.x;
    const int lane = tid & 31;
    const int wid  = tid >> 5;
    const int bx   = blockIdx.x;          // c tile 0..11
    const int by   = blockIdx.y;          // m tile 0..63
    const int b    = by >> 3;
    const int n0   = (by & 7) << 7;
    const int c0   = bx * 128;
    const uint32_t sbase = (uint32_t)__cvta_generic_to_shared(smq);

    // loader mapping: row lk (0..31), 16 u16 (32B) per plane per matrix
    const int lk  = tid >> 3;
    const int lmf = (tid & 7) * 16;
    const size_t aG = (size_t)b * CC * NN + n0 + lmf + (size_t)lk * NN;
    const size_t wG = (size_t)c0 + lmf + (size_t)lk * QKVC;
    const uint32_t dA = (uint32_t)(lk * 136 + lmf) * 2;

    const int wm = wid >> 2;
    const int wn = wid & 3;
    const uint32_t aOff = ((lane & 7) + ((lane >> 4) << 3)) * 272
                        + (uint32_t)(wm * 128) + ((lane >> 3) & 1) * 16;
    const uint32_t bOff = ((lane & 7) + (((lane >> 3) & 1) << 3)) * 272
                        + (uint32_t)(wn * 64) + (lane >> 4) * 16;

    float acc[4][4][4];
#pragma unroll
    for (int i = 0; i < 4; i++)
#pragma unroll
        for (int j = 0; j < 4; j++)
#pragma unroll
            for (int e = 0; e < 4; e++) acc[i][j][e] = 0.f;

#define QK_ISSUE(s) do {                                                      \
        uint32_t st = sbase + ((s) % 3) * QK_STG;                             \
        size_t ko = (size_t)(s) * 32;                                         \
        const uint16_t* ah = &g_xh[aG + ko * NN];                             \
        const uint16_t* wh = &g_wqh[wG + ko * QKVC];                          \
        cpa16(st + dA, ah);              cpa16(st + dA + 16, ah + 8);         \
        cpa16(st + dA + KBYTES, wh);     cpa16(st + dA + KBYTES + 16, wh + 8);\
    } while (0)

    QK_ISSUE(0); CP_COMMIT();
    QK_ISSUE(1); CP_COMMIT();

    for (int s = 0; s < 16; s++) {
        if (s < 15) CP_WAIT1(); else CP_WAIT0();
        __syncthreads();
        if (s + 2 < 16) { QK_ISSUE(s + 2); CP_COMMIT(); }

        const uint32_t base = sbase + (uint32_t)(s % 3) * QK_STG;
#pragma unroll
        for (int ks = 0; ks < 2; ks++) {
            uint32_t ahi[4][4], bhi[4][2];
#pragma unroll
            for (int i = 0; i < 4; i++) {
                uint32_t addr = base + aOff + ks * 4352 + i * 32;
                ldmx4t(addr, ahi[i][0], ahi[i][1], ahi[i][2], ahi[i][3]);
            }
#pragma unroll
            for (int j2 = 0; j2 < 2; j2++) {
                uint32_t addr = base + KBYTES + bOff + ks * 4352 + j2 * 32;
                ldmx4t(addr, bhi[2 * j2][0], bhi[2 * j2][1], bhi[2 * j2 + 1][0], bhi[2 * j2 + 1][1]);
            }
#pragma unroll
            for (int i = 0; i < 4; i++)
#pragma unroll
                for (int jn = 0; jn < 4; jn++)
                    mma16816(acc[i][jn], ahi[i], bhi[jn]);
        }
    }

    // ---- epilogue: bias, pre-scale Q columns, store fp16 ----
    const int g   = lane >> 2;
    const int tig = lane & 3;
#pragma unroll
    for (int i = 0; i < 4; i++) {
        int m = by * 128 + wm * 64 + i * 16 + g;
#pragma unroll
        for (int jn = 0; jn < 4; jn++) {
            int c = c0 + wn * 32 + jn * 8 + tig * 2;
            float2 bias = *(const float2*)&bq[c];
            float sc = ((c % 192) < 64) ? SCL2E : 1.f;
            float v0 = (acc[i][jn][0] + bias.x) * sc;
            float v1 = (acc[i][jn][1] + bias.y) * sc;
            float v2 = (acc[i][jn][2] + bias.x) * sc;
            float v3 = (acc[i][jn][3] + bias.y) * sc;
            *(uint32_t*)&g_qh[(size_t)m * QKVC + c]       = hi2(v0, v1);
            *(uint32_t*)&g_qh[(size_t)(m + 8) * QKVC + c] = hi2(v2, v3);
        }
    }
}

// ---------------------------------------------------------------------------
// Kernel 2: attention, tensor cores (fp16), 8 warps x 16 q-rows,
// K/V stages of 64 keys double-buffered.
// Smem: Qh (128x72 u16) + 2 stages of {Kh, Vh} (64x72 each) = 55296 B.
// ---------------------------------------------------------------------------
#define A_ST0   9216            // u16: stage region start (after Qh)
#define A_STG   9216            // u16 per stage (2 planes * 64*72)
#define A_VHIo  4608            // V within stage (u16)
#define A_SMEM_BYTES ((A_ST0 + 2 * A_STG) * 2)   // 55296 B

__global__ __launch_bounds__(256, 2) void k_attn()
{
    extern __shared__ __align__(16) uint16_t sma[];
    const int tid  = threadIdx.x;
    const int lane = tid & 31;
    const int wid  = tid >> 5;     // 0..7
    const int qt   = blockIdx.x;   // 0..7
    const int h    = blockIdx.y;
    const int b    = blockIdx.z;
    const size_t head = (size_t)b * NN * QKVC + (size_t)h * (3 * DK);
    const uint32_t sb = (uint32_t)__cvta_generic_to_shared(sma);

    // Q loader: row = tid>>1 (0..127), off = (tid&1)*32 u16 (4 chunks)
    const int qrow = tid >> 1;
    const int qoff = (tid & 1) * 32;
    const uint32_t dQ = (uint32_t)(qrow * 72 + qoff) * 2;
#define AT_ISSUE_Q() do {                                                     \
        size_t rr = head + (size_t)(qt * 128 + qrow) * QKVC + qoff;           \
        const uint16_t* qh_ = &g_qh[rr];                                      \
        _Pragma("unroll")                                                     \
        for (int cc = 0; cc < 4; cc++)                                        \
            cpa16(sb + dQ + cc * 16, qh_ + cc * 8);                           \
    } while (0)

    // KV loader: key row = tid>>2 (0..63), quarter-row 16 u16 (2 chunks/plane)
    const int lrow = tid >> 2;
    const int loff = (tid & 3) * 16;
    const uint32_t dKV = (uint32_t)(lrow * 72 + loff) * 2;
#define AT_ISSUE_KV(kt) do {                                                  \
        uint32_t st = sb + (A_ST0 + ((kt) & 1) * A_STG) * 2;                  \
        size_t rr = head + (size_t)((kt) * 64 + lrow) * QKVC + loff;          \
        const uint16_t* kh_ = &g_qh[rr + 64];                                 \
        const uint16_t* vh_ = &g_qh[rr + 128];                                \
        _Pragma("unroll")                                                     \
        for (int cc = 0; cc < 2; cc++) {                                      \
            cpa16(st + dKV + cc * 16,              kh_ + cc * 8);             \
            cpa16(st + dKV + A_VHIo * 2 + cc * 16, vh_ + cc * 8);             \
        }                                                                     \
    } while (0)

    AT_ISSUE_Q(); AT_ISSUE_KV(0); CP_COMMIT();
    AT_ISSUE_KV(1); CP_COMMIT();

    const uint32_t kOff = ((lane & 7) + ((lane >> 4) << 3)) * 144
                        + ((lane >> 3) & 1) * 16;                 // non-trans (K)
    const uint32_t vOff = ((lane & 7) + (((lane >> 3) & 1) << 3)) * 144
                        + (lane >> 4) * 16;                        // trans (V)

    uint32_t qf[4][4];
    float oacc[8][4];
#pragma unroll
    for (int i = 0; i < 8; i++)
#pragma unroll
        for (int e = 0; e < 4; e++) oacc[i][e] = 0.f;
    float li0 = 0.f, li1 = 0.f;

    for (int kt = 0; kt < 16; kt++) {
        if (kt < 15) CP_WAIT1(); else CP_WAIT0();
        __syncthreads();

        if (kt == 0) {
            const uint32_t qa = sb + (wid * 16 + (lane & 15)) * 144 + (lane >> 4) * 16;
#pragma unroll
            for (int j = 0; j < 4; j++) ldmx4(qa + j * 32, qf[j]);
        }

        const uint32_t stb = sb + (A_ST0 + (kt & 1) * A_STG) * 2;
        const uint32_t kB = stb + kOff;
        const uint32_t vB = stb + A_VHIo * 2 + vOff;

        // ---- fused per 16-key group: S (2 n8-tiles) -> exp -> P -> PV ----
#pragma unroll
        for (int nt2 = 0; nt2 < 4; nt2++) {
            float s0[4], s1[4];
#pragma unroll
            for (int e = 0; e < 4; e++) { s0[e] = 0.f; s1[e] = 0.f; }

#pragma unroll
            for (int j = 0; j < 4; j++) {
                uint32_t kh[4];
                uint32_t a = kB + nt2 * (16 * 144) + j * 32;
                ldmx4(a, kh);
                mma_b(s0, qf[j], kh[0], kh[1]);
                mma_b(s1, qf[j], kh[2], kh[3]);
            }

#pragma unroll
            for (int e = 0; e < 4; e++) { s0[e] = ex2(s0[e]); s1[e] = ex2(s1[e]); }
            li0 += (s0[0] + s0[1]) + (s1[0] + s1[1]);
            li1 += (s0[2] + s0[3]) + (s1[2] + s1[3]);

            uint32_t ph[4];
            ph[0] = hi2(s0[0], s0[1]); ph[1] = hi2(s0[2], s0[3]);
            ph[2] = hi2(s1[0], s1[1]); ph[3] = hi2(s1[2], s1[3]);

#pragma unroll
            for (int dt2 = 0; dt2 < 4; dt2++) {
                uint32_t vh0, vh1, vh2, vh3;
                uint32_t a = vB + nt2 * (16 * 144) + dt2 * 32;
                ldmx4t(a, vh0, vh1, vh2, vh3);
                mma_b(oacc[2 * dt2],     ph, vh0, vh1);
                mma_b(oacc[2 * dt2 + 1], ph, vh2, vh3);
            }
        }

        __syncthreads();
        if (kt + 2 < 16) { AT_ISSUE_KV(kt + 2); CP_COMMIT(); }
    }

    // ---- reduce row sums over the 4 quad lanes, normalize, write fp16 ----
    li0 += __shfl_xor_sync(0xffffffffu, li0, 1);
    li0 += __shfl_xor_sync(0xffffffffu, li0, 2);
    li1 += __shfl_xor_sync(0xffffffffu, li1, 1);
    li1 += __shfl_xor_sync(0xffffffffu, li1, 2);
    const float inv0 = 1.f / li0;
    const float inv1 = 1.f / li1;

    const int g   = lane >> 2;
    const int tig = lane & 3;
    const int row = qt * 128 + wid * 16 + g;
    const size_t r0 = (size_t)(b * NN + row) * CC + h * 64 + tig * 2;
    const size_t r1 = r0 + (size_t)8 * CC;
#pragma unroll
    for (int dt = 0; dt < 8; dt++) {
        *(uint32_t*)&g_ah[r0 + dt * 8] = hi2(oacc[dt][0] * inv0, oacc[dt][1] * inv0);
        *(uint32_t*)&g_ah[r1 + dt * 8] = hi2(oacc[dt][2] * inv1, oacc[dt][3] * inv1);
    }
}

// ---------------------------------------------------------------------------
// Kernel 3: out = att @ W_out + b_out + residual (fp16), cp.async 3-stage;
// smem-transpose epilogue with fused bias+residual.
// Stage planes: Ah (128x40 u16 = 10240 B), Bh (32x136 u16 = 8704 B).
// ---------------------------------------------------------------------------
#define PJ_BHI    10240    // byte offset within a stage
#define PJ_STAGEB 18944
#define PJ_SMEM   67584    // max(3 stages = 56832, transpose 128*132*4 = 67584)

__global__ __launch_bounds__(256, 1) void k_proj(const float* __restrict__ bo,
                                                 const float* __restrict__ x,
                                                 float* __restrict__ out)
{
    extern __shared__ __align__(16) uint16_t smp[];
    const int tid  = threadIdx.x;
    const int lane = tid & 31;
    const int wid  = tid >> 5;
    const int bx   = blockIdx.x;    // bn tile 0..63
    const int by   = blockIdx.y;    // c tile 0..3
    const int b    = bx >> 3;
    const int c0   = by * 128;
    const int bn0  = bx * 128;
    const uint32_t sb = (uint32_t)__cvta_generic_to_shared(smp);

    // loader mapping
    const int am = tid >> 1;
    const int ak = (tid & 1) * 16;            // u16
    const size_t aG = (size_t)(bn0 + am) * CC + ak;
    const int bk = tid >> 3;
    const int bn = (tid & 7) * 16;            // u16
    const size_t bG = (size_t)bk * CC + c0 + bn;
    const uint32_t dAp = (uint32_t)(am * 40 + ak) * 2;
    const uint32_t dBp = PJ_BHI + (uint32_t)(bk * 136 + bn) * 2;

#define PJ_ISSUE(s) do {                                                      \
        uint32_t st = sb + ((s) % 3) * PJ_STAGEB;                             \
        const uint16_t* ah = &g_ah[aG + (s) * 32];                            \
        const uint16_t* bh = &g_woh[bG + (size_t)(s) * 32 * CC];              \
        cpa16(st + dAp, ah);             cpa16(st + dAp + 16, ah + 8);        \
        cpa16(st + dBp, bh);             cpa16(st + dBp + 16, bh + 8);        \
    } while (0)

    const int wm = wid >> 2;
    const int wn = wid & 3;
    const uint32_t aOff = (wm * 64 + (lane & 15)) * 80 + (lane >> 4) * 16;
    const uint32_t bOff = PJ_BHI + ((lane & 7) + (((lane >> 3) & 1) << 3)) * 272
                        + (uint32_t)(wn * 64) + (lane >> 4) * 16;

    float acc[4][4][4];
#pragma unroll
    for (int i = 0; i < 4; i++)
#pragma unroll
        for (int j = 0; j < 4; j++)
#pragma unroll
            for (int e = 0; e < 4; e++) acc[i][j][e] = 0.f;

    PJ_ISSUE(0); CP_COMMIT();
    PJ_ISSUE(1); CP_COMMIT();

    for (int s = 0; s < 16; s++) {
        if (s < 15) CP_WAIT1(); else CP_WAIT0();
        __syncthreads();
        if (s + 2 < 16) { PJ_ISSUE(s + 2); CP_COMMIT(); }

        const uint32_t base = sb + (uint32_t)(s % 3) * PJ_STAGEB;
#pragma unroll
        for (int ks = 0; ks < 2; ks++) {
            uint32_t ahi[4][4], bhi[4][2];
#pragma unroll
            for (int i = 0; i < 4; i++) {
                uint32_t a = base + aOff + i * (16 * 80) + ks * 32;
                ldmx4(a, ahi[i]);
            }
#pragma unroll
            for (int j2 = 0; j2 < 2; j2++) {
                uint32_t a = base + bOff + ks * 4352 + j2 * 32;
                ldmx4t(a, bhi[2 * j2][0], bhi[2 * j2][1], bhi[2 * j2 + 1][0], bhi[2 * j2 + 1][1]);
            }
#pragma unroll
            for (int i = 0; i < 4; i++)
#pragma unroll
                for (int jn = 0; jn < 4; jn++)
                    mma16816(acc[i][jn], ahi[i], bhi[jn]);
        }
    }

    // ---- epilogue: transpose via smem, fused bias + residual ----
    __syncthreads();
    float* S = (float*)smp;   // [128 c][stride 132] of m
    const int g   = lane >> 2;
    const int tig = lane & 3;
#pragma unroll
    for (int i = 0; i < 4; i++) {
        int m_l = wm * 64 + i * 16 + g;
#pragma unroll
        for (int jn = 0; jn < 4; jn++) {
            int c_l = wn * 32 + jn * 8 + tig * 2;
            S[c_l * 132 + m_l]           = acc[i][jn][0];
            S[(c_l + 1) * 132 + m_l]     = acc[i][jn][1];
            S[c_l * 132 + m_l + 8]       = acc[i][jn][2];
            S[(c_l + 1) * 132 + m_l + 8] = acc[i][jn][3];
        }
    }
    __syncthreads();
    {
        const int c_l  = tid >> 1;
        const int mseg = (tid & 1) * 64;
        const int c    = c0 + c_l;
        const float bias = bo[c];
        const int n0 = (bx & 7) * 128;
        const size_t basep = (size_t)b * CC * NN + (size_t)c * NN + n0 + mseg;
#pragma unroll
        for (int i = 0; i < 16; i++) {
            float4 v  = *(float4*)&S[c_l * 132 + mseg + 4 * i];
            float4 xr = *(const float4*)&x[basep + 4 * i];
            v.x += bias + xr.x; v.y += bias + xr.y;
            v.z += bias + xr.z; v.w += bias + xr.w;
            *(float4*)&out[basep + 4 * i] = v;
        }
    }
}

// ---------------------------------------------------------------------------
extern "C" void kernel_launch(void* const* d_in, const int* in_sizes, int n_in,
                              void* d_out, int out_size)
{
    const float* x  = (const float*)d_in[0];
    const float* Wq = (const float*)d_in[1];
    const float* bq = (const float*)d_in[2];
    const float* Wo = (const float*)d_in[3];
    const float* bo = (const float*)d_in[4];
    float* out = (float*)d_out;

    k_cvt<<<(BB * CC * NN / 4 + 255) / 256, 256>>>(x, 0, BB * CC * NN / 4);
    k_cvt<<<(CC * QKVC / 4 + 255) / 256, 256>>>(Wq, 1, CC * QKVC / 4);
    k_cvt<<<(CC * CC / 4 + 255) / 256, 256>>>(Wo, 2, CC * CC / 4);

    cudaFuncSetAttribute(k_qkv, cudaFuncAttributeMaxDynamicSharedMemorySize, QK_SMEM);
    k_qkv<<<dim3(12, 64), 256, QK_SMEM>>>(bq);

    cudaFuncSetAttribute(k_attn, cudaFuncAttributeMaxDynamicSharedMemorySize, A_SMEM_BYTES);
    k_attn<<<dim3(8, HEADS, BB), 256, A_SMEM_BYTES>>>();

    cudaFuncSetAttribute(k_proj, cudaFuncAttributeMaxDynamicSharedMemorySize, PJ_SMEM);
    k_proj<<<dim3(64, 4), 256, PJ_SMEM>>>(bo, x, out);
}